// round 1
// baseline (speedup 1.0000x reference)
#include <cuda_runtime.h>
#include <cuda_bf16.h>
#include <math.h>

// Problem dims
#define BB 8
#define SS 128
#define EE 512
#define DD 1024
#define HH 16
#define LL 4
#define VV 32000
#define DHH 64
#define FF_ 4096
#define TT (SS*BB)          // 1024 decoder tokens, row t = s*B + b
#define TE (EE*BB)          // 4096 encoder tokens, row t = e*B + b
#define SCALE_ 0.125f
#define NEG_ (-1e30f)

// ---------------- scratch (__device__ globals; no allocation allowed) ----------------
__device__ float g_r[SS*DD];
__device__ float g_rk[SS*DD];
__device__ float g_core[TT*DD];
__device__ float g_x[TT*DD];
__device__ float g_y[TT*DD];
__device__ float g_tmp[TT*DD];
__device__ float g_vec[TT*DD];
__device__ float g_q2[TT*DD];
__device__ float g_outb[TT*DD];
__device__ float g_copyh[TT*DD];
__device__ float g_enct[TE*DD];
__device__ float g_heads[TT*3*DD];
__device__ float g_kv[TE*2*DD];
__device__ float g_AC[BB*HH*SS*SS];
__device__ float g_BD[BB*HH*SS*SS];
__device__ float g_s2[BB*HH*SS*EE];
__device__ float g_h[TT*FF_];
__device__ float g_logits[(size_t)TT*VV];
__device__ float g_IL[TT*EE];
__device__ float g_rmax[TT];
__device__ float g_rsum[TT];
__device__ float g_msig[TT];

// ---------------- generic NT SGEMM: C[m,n] = sum_k A[m,k]*Bw[n,k] (+bias, +act) -----
// BM=BN=128, BK=16, 256 threads, 8x8 microtile, transposed smem tiles.
__global__ __launch_bounds__(256, 2)
void sgemm_nt(const float* __restrict__ A, const float* __restrict__ Bw,
              float* __restrict__ C, const float* __restrict__ bias,
              int K, int lda, int ldb, int ldc, int act)
{
    __shared__ float As[16][132];
    __shared__ float Bs[16][132];
    int tid = threadIdx.x;
    int tx = tid & 15, ty = tid >> 4;
    int m0 = ty * 8, n0 = tx * 8;
    int rowA0 = blockIdx.y * 128;
    int colB0 = blockIdx.x * 128;
    int r  = tid >> 2;
    int c4 = (tid & 3) * 4;
    float acc[8][8];
#pragma unroll
    for (int i = 0; i < 8; i++)
#pragma unroll
        for (int j = 0; j < 8; j++) acc[i][j] = 0.f;

    for (int kb = 0; kb < K; kb += 16) {
#pragma unroll
        for (int half = 0; half < 2; half++) {
            int rr = r + half * 64;
            float4 av = *reinterpret_cast<const float4*>(&A[(size_t)(rowA0 + rr) * lda + kb + c4]);
            As[c4+0][rr] = av.x; As[c4+1][rr] = av.y; As[c4+2][rr] = av.z; As[c4+3][rr] = av.w;
            float4 bv = *reinterpret_cast<const float4*>(&Bw[(size_t)(colB0 + rr) * ldb + kb + c4]);
            Bs[c4+0][rr] = bv.x; Bs[c4+1][rr] = bv.y; Bs[c4+2][rr] = bv.z; Bs[c4+3][rr] = bv.w;
        }
        __syncthreads();
#pragma unroll
        for (int kk = 0; kk < 16; kk++) {
            float a[8], b[8];
            *reinterpret_cast<float4*>(a)     = *reinterpret_cast<const float4*>(&As[kk][m0]);
            *reinterpret_cast<float4*>(a + 4) = *reinterpret_cast<const float4*>(&As[kk][m0 + 4]);
            *reinterpret_cast<float4*>(b)     = *reinterpret_cast<const float4*>(&Bs[kk][n0]);
            *reinterpret_cast<float4*>(b + 4) = *reinterpret_cast<const float4*>(&Bs[kk][n0 + 4]);
#pragma unroll
            for (int i = 0; i < 8; i++)
#pragma unroll
                for (int j = 0; j < 8; j++) acc[i][j] += a[i] * b[j];
        }
        __syncthreads();
    }
#pragma unroll
    for (int i = 0; i < 8; i++) {
        int gm = rowA0 + m0 + i;
#pragma unroll
        for (int j = 0; j < 8; j++) {
            int gn = colB0 + n0 + j;
            float v = acc[i][j];
            if (bias) v += bias[gn];
            if (act == 1) v = 0.5f * v * (1.0f + erff(v * 0.70710678118654752f));
            C[(size_t)gm * ldc + gn] = v;
        }
    }
}

// ---------------- batched NT gemm (M=128): C[i,n] = sum_k (A[i,k]+abias[k]) * B[n,k]
__global__ __launch_bounds__(256, 2)
void bgemm_nt(const float* __restrict__ A, const float* __restrict__ Bp,
              float* __restrict__ C, const float* __restrict__ abias,
              int K, int Hdim,
              long long aSB, long long aSH, int aRow,
              long long bSB, long long bSH, int bRow,
              long long cSB, long long cSH, int cRow, int abiasH)
{
    __shared__ float As[16][132];
    __shared__ float Bs[16][132];
    int z = blockIdx.z;
    int h = z % Hdim, b = z / Hdim;
    const float* Ab = A + (size_t)b * aSB + (size_t)h * aSH;
    const float* Bb = Bp + (size_t)b * bSB + (size_t)h * bSH;
    float* Cb = C + (size_t)b * cSB + (size_t)h * cSH;
    const float* biasb = abias ? (abias + (size_t)h * abiasH) : nullptr;

    int tid = threadIdx.x;
    int tx = tid & 15, ty = tid >> 4;
    int m0 = ty * 8, n0 = tx * 8;
    int colB0 = blockIdx.x * 128;
    int r  = tid >> 2;
    int c4 = (tid & 3) * 4;
    float acc[8][8];
#pragma unroll
    for (int i = 0; i < 8; i++)
#pragma unroll
        for (int j = 0; j < 8; j++) acc[i][j] = 0.f;

    for (int kb = 0; kb < K; kb += 16) {
        float4 biasv = make_float4(0.f, 0.f, 0.f, 0.f);
        if (biasb) biasv = *reinterpret_cast<const float4*>(&biasb[kb + c4]);
#pragma unroll
        for (int half = 0; half < 2; half++) {
            int rr = r + half * 64;
            float4 av = *reinterpret_cast<const float4*>(&Ab[(size_t)rr * aRow + kb + c4]);
            As[c4+0][rr] = av.x + biasv.x; As[c4+1][rr] = av.y + biasv.y;
            As[c4+2][rr] = av.z + biasv.z; As[c4+3][rr] = av.w + biasv.w;
            float4 bv = *reinterpret_cast<const float4*>(&Bb[(size_t)(colB0 + rr) * bRow + kb + c4]);
            Bs[c4+0][rr] = bv.x; Bs[c4+1][rr] = bv.y; Bs[c4+2][rr] = bv.z; Bs[c4+3][rr] = bv.w;
        }
        __syncthreads();
#pragma unroll
        for (int kk = 0; kk < 16; kk++) {
            float a[8], bb[8];
            *reinterpret_cast<float4*>(a)      = *reinterpret_cast<const float4*>(&As[kk][m0]);
            *reinterpret_cast<float4*>(a + 4)  = *reinterpret_cast<const float4*>(&As[kk][m0 + 4]);
            *reinterpret_cast<float4*>(bb)     = *reinterpret_cast<const float4*>(&Bs[kk][n0]);
            *reinterpret_cast<float4*>(bb + 4) = *reinterpret_cast<const float4*>(&Bs[kk][n0 + 4]);
#pragma unroll
            for (int i = 0; i < 8; i++)
#pragma unroll
                for (int j = 0; j < 8; j++) acc[i][j] += a[i] * bb[j];
        }
        __syncthreads();
    }
#pragma unroll
    for (int i = 0; i < 8; i++)
#pragma unroll
        for (int j = 0; j < 8; j++)
            Cb[(size_t)(m0 + i) * cRow + colB0 + n0 + j] = acc[i][j];
}

// ---------------- batched NN gemm (M=128, N=64): C[i,d] = sum_j A[i,j]*B[j,d] -------
__global__ __launch_bounds__(256, 2)
void bgemm_nn(const float* __restrict__ A, const float* __restrict__ Bp,
              float* __restrict__ C,
              int K, int Hdim,
              long long aSB, long long aSH, int aRow,
              long long bSB, long long bSH, int bRow,
              long long cSB, long long cSH, int cRow)
{
    __shared__ float As[16][132];
    __shared__ float Bs[16][68];
    int z = blockIdx.z;
    int h = z % Hdim, b = z / Hdim;
    const float* Ab = A + (size_t)b * aSB + (size_t)h * aSH;
    const float* Bb = Bp + (size_t)b * bSB + (size_t)h * bSH;
    float* Cb = C + (size_t)b * cSB + (size_t)h * cSH;

    int tid = threadIdx.x;
    int tx = tid & 15, ty = tid >> 4;
    int m0 = ty * 8, n0 = tx * 4;
    int rA = tid >> 2, c4A = (tid & 3) * 4;
    int rB = tid >> 4, c4B = (tid & 15) * 4;
    float acc[8][4];
#pragma unroll
    for (int i = 0; i < 8; i++)
#pragma unroll
        for (int j = 0; j < 4; j++) acc[i][j] = 0.f;

    for (int kb = 0; kb < K; kb += 16) {
#pragma unroll
        for (int half = 0; half < 2; half++) {
            int rr = rA + half * 64;
            float4 av = *reinterpret_cast<const float4*>(&Ab[(size_t)rr * aRow + kb + c4A]);
            As[c4A+0][rr] = av.x; As[c4A+1][rr] = av.y; As[c4A+2][rr] = av.z; As[c4A+3][rr] = av.w;
        }
        *reinterpret_cast<float4*>(&Bs[rB][c4B]) =
            *reinterpret_cast<const float4*>(&Bb[(size_t)(kb + rB) * bRow + c4B]);
        __syncthreads();
#pragma unroll
        for (int kk = 0; kk < 16; kk++) {
            float a[8], bb[4];
            *reinterpret_cast<float4*>(a)     = *reinterpret_cast<const float4*>(&As[kk][m0]);
            *reinterpret_cast<float4*>(a + 4) = *reinterpret_cast<const float4*>(&As[kk][m0 + 4]);
            *reinterpret_cast<float4*>(bb)    = *reinterpret_cast<const float4*>(&Bs[kk][n0]);
#pragma unroll
            for (int i = 0; i < 8; i++)
#pragma unroll
                for (int j = 0; j < 4; j++) acc[i][j] += a[i] * bb[j];
        }
        __syncthreads();
    }
#pragma unroll
    for (int i = 0; i < 8; i++)
#pragma unroll
        for (int j = 0; j < 4; j++)
            Cb[(size_t)(m0 + i) * cRow + n0 + j] = acc[i][j];
}

// ---------------- misc small kernels --------------------------------------------------
__global__ void pos_emb_kernel(float* __restrict__ r)
{
    int i = blockIdx.x;
    float pos = (float)(SS - 1 - i);
    const float LOG1E4 = 9.210340371976184f; // ln(10000)
    for (int d = threadIdx.x; d < DD; d += 256) {
        int j = (d < DD/2) ? d : d - DD/2;
        float invf = expf(-((float)j / (DD/2)) * LOG1E4);
        float a = pos * invf;
        r[i * DD + d] = (d < DD/2) ? sinf(a) : cosf(a);
    }
}

__global__ void embed_kernel(const int* __restrict__ dec, const float* __restrict__ emb,
                             float* __restrict__ core)
{
    int t = blockIdx.x;          // t = s*B + b
    int b = t & (BB-1), s = t >> 3;
    int id = dec[b * SS + s];
    const float* src = emb + (size_t)id * DD;
    float* dst = core + (size_t)t * DD;
    for (int d = threadIdx.x; d < DD; d += 256) dst[d] = src[d];
}

__global__ void transpose_enc(const float* __restrict__ enc, float* __restrict__ enct)
{
    int t = blockIdx.x;          // t = e*B + b
    int b = t & (BB-1), e = t >> 3;
    const float* src = enc + ((size_t)b * EE + e) * DD;
    float* dst = enct + (size_t)t * DD;
    for (int d = threadIdx.x; d < DD; d += 256) dst[d] = src[d];
}

// self-attn: score = (AC + relshift(BD))*SCALE, causal mask, softmax over j. In-place into AC.
__global__ void softmax_self(const float* __restrict__ AC, const float* __restrict__ BD,
                             float* __restrict__ P)
{
    int row = blockIdx.x;        // (b*H+h)*S + i
    int i = row & (SS - 1);
    int bhBase = row - i;
    int j = threadIdx.x;         // 128
    float acv = AC[(size_t)row * SS + j];
    int f = i * SS + j + SS;
    int qi = f / (SS + 1), c = f % (SS + 1);
    float bd = (c > 0) ? BD[(size_t)(bhBase + qi) * SS + (c - 1)] : 0.0f;
    float s = (acv + bd) * SCALE_;
    if (j > i) s = NEG_;
    __shared__ float sh[128];
    sh[j] = s; __syncthreads();
    for (int st = 64; st > 0; st >>= 1) { if (j < st) sh[j] = fmaxf(sh[j], sh[j + st]); __syncthreads(); }
    float mx = sh[0]; __syncthreads();
    float e = expf(s - mx);
    sh[j] = e; __syncthreads();
    for (int st = 64; st > 0; st >>= 1) { if (j < st) sh[j] += sh[j + st]; __syncthreads(); }
    P[(size_t)row * SS + j] = e / sh[0];
}

// cross-attn: score*SCALE + (1-mask)*NEG, softmax over E. In-place.
__global__ void softmax_cross(float* __restrict__ S2, const float* __restrict__ mask)
{
    int row = blockIdx.x;        // (b*H+h)*S + i, 16384 rows
    int b = row / (HH * SS);
    int k = threadIdx.x;         // 512
    float v = S2[(size_t)row * EE + k] * SCALE_ + (1.0f - mask[b * EE + k]) * NEG_;
    __shared__ float sh[512];
    sh[k] = v; __syncthreads();
    for (int st = 256; st > 0; st >>= 1) { if (k < st) sh[k] = fmaxf(sh[k], sh[k + st]); __syncthreads(); }
    float mx = sh[0]; __syncthreads();
    float e = expf(v - mx);
    sh[k] = e; __syncthreads();
    for (int st = 256; st > 0; st >>= 1) { if (k < st) sh[k] += sh[k + st]; __syncthreads(); }
    S2[(size_t)row * EE + k] = e / sh[0];
}

// copy-attn softmax over E with mask, rows t=s*B+b. In-place.
__global__ void softmax_il(float* __restrict__ IL, const float* __restrict__ mask)
{
    int t = blockIdx.x;
    int b = t & (BB - 1);
    int k = threadIdx.x;         // 512
    float v = IL[(size_t)t * EE + k] + (1.0f - mask[b * EE + k]) * NEG_;
    __shared__ float sh[512];
    sh[k] = v; __syncthreads();
    for (int st = 256; st > 0; st >>= 1) { if (k < st) sh[k] = fmaxf(sh[k], sh[k + st]); __syncthreads(); }
    float mx = sh[0]; __syncthreads();
    float e = expf(v - mx);
    sh[k] = e; __syncthreads();
    for (int st = 256; st > 0; st >>= 1) { if (k < st) sh[k] += sh[k + st]; __syncthreads(); }
    IL[(size_t)t * EE + k] = e / sh[0];
}

// out = LayerNorm(resid + add) * g + b
__global__ void add_ln(const float* __restrict__ resid, const float* __restrict__ add,
                       float* __restrict__ out, const float* __restrict__ g,
                       const float* __restrict__ bta)
{
    int t = blockIdx.x;
    int tid = threadIdx.x;       // 256
    __shared__ float zb[DD];
    __shared__ float red[256];
    float s = 0.f;
#pragma unroll
    for (int u = 0; u < 4; u++) {
        int d = tid + u * 256;
        float z = resid[(size_t)t * DD + d] + add[(size_t)t * DD + d];
        zb[d] = z; s += z;
    }
    red[tid] = s; __syncthreads();
    for (int st = 128; st > 0; st >>= 1) { if (tid < st) red[tid] += red[tid + st]; __syncthreads(); }
    float mean = red[0] * (1.0f / DD); __syncthreads();
    float v = 0.f;
#pragma unroll
    for (int u = 0; u < 4; u++) {
        int d = tid + u * 256;
        float dz = zb[d] - mean; v += dz * dz;
    }
    red[tid] = v; __syncthreads();
    for (int st = 128; st > 0; st >>= 1) { if (tid < st) red[tid] += red[tid + st]; __syncthreads(); }
    float inv = rsqrtf(red[0] * (1.0f / DD) + 1e-5f);
#pragma unroll
    for (int u = 0; u < 4; u++) {
        int d = tid + u * 256;
        out[(size_t)t * DD + d] = (zb[d] - mean) * inv * g[d] + bta[d];
    }
}

__global__ void row_logit_stats(const float* __restrict__ Lg, float* __restrict__ rmax,
                                float* __restrict__ rsum)
{
    int t = blockIdx.x;
    int tid = threadIdx.x;       // 256
    const float* row = Lg + (size_t)t * VV;
    float m = -1e30f;
    for (int v = tid; v < VV; v += 256) m = fmaxf(m, row[v]);
    __shared__ float red[256];
    red[tid] = m; __syncthreads();
    for (int st = 128; st > 0; st >>= 1) { if (tid < st) red[tid] = fmaxf(red[tid], red[tid + st]); __syncthreads(); }
    m = red[0]; __syncthreads();
    float s = 0.f;
    for (int v = tid; v < VV; v += 256) s += expf(row[v] - m);
    red[tid] = s; __syncthreads();
    for (int st = 128; st > 0; st >>= 1) { if (tid < st) red[tid] += red[tid + st]; __syncthreads(); }
    if (tid == 0) { rmax[t] = m; rsum[t] = red[0]; }
}

__global__ void mode_kernel(const float* __restrict__ core, const float* __restrict__ mw,
                            const float* __restrict__ mb, float* __restrict__ msig)
{
    int t = blockIdx.x;
    int tid = threadIdx.x;       // 256
    float s = 0.f;
    for (int d = tid; d < DD; d += 256) s += core[(size_t)t * DD + d] * mw[d];
    __shared__ float red[256];
    red[tid] = s; __syncthreads();
    for (int st = 128; st > 0; st >>= 1) { if (tid < st) red[tid] += red[tid + st]; __syncthreads(); }
    if (tid == 0) msig[t] = 1.0f / (1.0f + expf(-(red[0] + mb[0])));
}

__global__ void loss_kernel(const float* __restrict__ logits, const float* __restrict__ rmax,
                            const float* __restrict__ rsum, const float* __restrict__ msig,
                            const float* __restrict__ IL, const int* __restrict__ input_ids,
                            const int* __restrict__ decode_target, float* __restrict__ out)
{
    int tid = threadIdx.x;       // 256
    float acc = 0.f, cnt = 0.f;
    for (int t = tid; t < TT; t += 256) {
        int b = t & (BB - 1), s = t >> 3;
        int tgt = decode_target[b * SS + s];
        if (tgt == 0) continue;
        float m = msig[t];
        float p = expf(logits[(size_t)t * VV + tgt] - rmax[t]) / rsum[t] * m;
        const int* ids = input_ids + b * EE;
        const float* il = IL + (size_t)t * EE;
        float cp = 0.f;
        for (int j = 0; j < EE; j++) if (ids[j] == tgt) cp += il[j];
        p += (1.0f - m) * cp;
        acc += -logf(p + 1e-6f);
        cnt += 1.0f;
    }
    __shared__ float sa[256], sc[256];
    sa[tid] = acc; sc[tid] = cnt; __syncthreads();
    for (int st = 128; st > 0; st >>= 1) {
        if (tid < st) { sa[tid] += sa[tid + st]; sc[tid] += sc[tid + st]; }
        __syncthreads();
    }
    if (tid < BB) out[tid] = sa[0] / sc[0];
}

// ---------------- host orchestration --------------------------------------------------
static float* symaddr(const void* sym)
{
    void* p = nullptr;
    cudaGetSymbolAddress(&p, sym);
    return (float*)p;
}

extern "C" void kernel_launch(void* const* d_in, const int* in_sizes, int n_in,
                              void* d_out, int out_size)
{
    const int*   input_ids     = (const int*)d_in[0];
    const float* encoder_rep   = (const float*)d_in[1];
    const float* input_mask    = (const float*)d_in[2];
    const int*   decode_input  = (const int*)d_in[3];
    const int*   decode_target = (const int*)d_in[4];
    const float* word_emb      = (const float*)d_in[5];
    const float* qkv_w         = (const float*)d_in[6];
    const float* r_w           = (const float*)d_in[7];
    const float* o_w           = (const float*)d_in[8];
    const float* kv_w          = (const float*)d_in[9];
    const float* q_w           = (const float*)d_in[10];
    const float* io_w          = (const float*)d_in[11];
    const float* rr_bias       = (const float*)d_in[12];
    const float* rw_bias       = (const float*)d_in[13];
    const float* ln1_g         = (const float*)d_in[14];
    const float* ln1_b         = (const float*)d_in[15];
    const float* ln2_g         = (const float*)d_in[16];
    const float* ln2_b         = (const float*)d_in[17];
    const float* ffn_w1        = (const float*)d_in[18];
    const float* ffn_b1        = (const float*)d_in[19];
    const float* ffn_w2        = (const float*)d_in[20];
    const float* ffn_b2        = (const float*)d_in[21];
    const float* ln3_g         = (const float*)d_in[22];
    const float* ln3_b         = (const float*)d_in[23];
    const float* out_w         = (const float*)d_in[24];
    const float* out_b         = (const float*)d_in[25];
    const float* copy_w        = (const float*)d_in[26];
    const float* copy_b        = (const float*)d_in[27];
    const float* mode_w        = (const float*)d_in[28];
    const float* mode_b        = (const float*)d_in[29];

    float* p_r     = symaddr(g_r);
    float* p_rk    = symaddr(g_rk);
    float* p_core  = symaddr(g_core);
    float* p_x     = symaddr(g_x);
    float* p_y     = symaddr(g_y);
    float* p_tmp   = symaddr(g_tmp);
    float* p_vec   = symaddr(g_vec);
    float* p_q2    = symaddr(g_q2);
    float* p_out   = symaddr(g_outb);
    float* p_copyh = symaddr(g_copyh);
    float* p_enct  = symaddr(g_enct);
    float* p_heads = symaddr(g_heads);
    float* p_kv    = symaddr(g_kv);
    float* p_AC    = symaddr(g_AC);
    float* p_BD    = symaddr(g_BD);
    float* p_s2    = symaddr(g_s2);
    float* p_h     = symaddr(g_h);
    float* p_log   = symaddr(g_logits);
    float* p_IL    = symaddr(g_IL);
    float* p_rmax  = symaddr(g_rmax);
    float* p_rsum  = symaddr(g_rsum);
    float* p_msig  = symaddr(g_msig);

    pos_emb_kernel<<<SS, 256>>>(p_r);
    embed_kernel<<<TT, 256>>>(decode_input, word_emb, p_core);
    transpose_enc<<<TE, 256>>>(encoder_rep, p_enct);

    for (int l = 0; l < LL; l++) {
        // heads = core @ qkv_w[l].T   [1024, 3072]
        sgemm_nt<<<dim3(3*DD/128, TT/128), 256>>>(p_core, qkv_w + (size_t)l*3*DD*DD, p_heads,
                                                  nullptr, DD, DD, DD, 3*DD, 0);
        // r_k = r @ r_w[l].T          [128, 1024]
        sgemm_nt<<<dim3(DD/128, SS/128), 256>>>(p_r, r_w + (size_t)l*DD*DD, p_rk,
                                                nullptr, DD, DD, DD, DD, 0);
        // AC[b,h,i,j] = (q + rw_bias) . k
        bgemm_nt<<<dim3(1, 1, BB*HH), 256>>>(p_heads, p_heads + DD, p_AC, rw_bias + (size_t)l*HH*DHH,
            DHH, HH,
            3*DD, DHH, BB*3*DD,
            3*DD, DHH, BB*3*DD,
            (long long)HH*SS*SS, (long long)SS*SS, SS, DHH);
        // BD[b,h,i,j] = (q + rr_bias) . r_k
        bgemm_nt<<<dim3(1, 1, BB*HH), 256>>>(p_heads, p_rk, p_BD, rr_bias + (size_t)l*HH*DHH,
            DHH, HH,
            3*DD, DHH, BB*3*DD,
            0, DHH, DD,
            (long long)HH*SS*SS, (long long)SS*SS, SS, DHH);
        softmax_self<<<BB*HH*SS, 128>>>(p_AC, p_BD, p_AC);
        // vec = prob @ v
        bgemm_nn<<<dim3(1, 1, BB*HH), 256>>>(p_AC, p_heads + 2*DD, p_vec,
            SS, HH,
            (long long)HH*SS*SS, (long long)SS*SS, SS,
            3*DD, DHH, BB*3*DD,
            DD, DHH, BB*DD);
        // x = LN(core + vec @ o_w.T)
        sgemm_nt<<<dim3(DD/128, TT/128), 256>>>(p_vec, o_w + (size_t)l*DD*DD, p_tmp,
                                                nullptr, DD, DD, DD, DD, 0);
        add_ln<<<TT, 256>>>(p_core, p_tmp, p_x, ln1_g + l*DD, ln1_b + l*DD);

        // cross attention
        sgemm_nt<<<dim3(2*DD/128, TE/128), 256>>>(p_enct, kv_w + (size_t)l*2*DD*DD, p_kv,
                                                  nullptr, DD, DD, DD, 2*DD, 0);
        sgemm_nt<<<dim3(DD/128, TT/128), 256>>>(p_x, q_w + (size_t)l*DD*DD, p_q2,
                                                nullptr, DD, DD, DD, DD, 0);
        bgemm_nt<<<dim3(EE/128, 1, BB*HH), 256>>>(p_q2, p_kv, p_s2, nullptr,
            DHH, HH,
            DD, DHH, BB*DD,
            2*DD, DHH, BB*2*DD,
            (long long)HH*SS*EE, (long long)SS*EE, EE, 0);
        softmax_cross<<<BB*HH*SS, 512>>>(p_s2, input_mask);
        bgemm_nn<<<dim3(1, 1, BB*HH), 256>>>(p_s2, p_kv + DD, p_vec,
            EE, HH,
            (long long)HH*SS*EE, (long long)SS*EE, EE,
            2*DD, DHH, BB*2*DD,
            DD, DHH, BB*DD);
        sgemm_nt<<<dim3(DD/128, TT/128), 256>>>(p_vec, io_w + (size_t)l*DD*DD, p_tmp,
                                                nullptr, DD, DD, DD, DD, 0);
        add_ln<<<TT, 256>>>(p_x, p_tmp, p_y, ln2_g + l*DD, ln2_b + l*DD);

        // FFN
        sgemm_nt<<<dim3(FF_/128, TT/128), 256>>>(p_y, ffn_w1 + (size_t)l*FF_*DD, p_h,
                                                 ffn_b1 + (size_t)l*FF_, DD, DD, DD, FF_, 1);
        sgemm_nt<<<dim3(DD/128, TT/128), 256>>>(p_h, ffn_w2 + (size_t)l*DD*FF_, p_tmp,
                                                ffn_b2 + (size_t)l*DD, FF_, FF_, FF_, DD, 0);
        add_ln<<<TT, 256>>>(p_y, p_tmp, p_core, ln3_g + l*DD, ln3_b + l*DD);
    }

    // output head
    sgemm_nt<<<dim3(DD/128, TT/128), 256>>>(p_core, out_w, p_out, out_b, DD, DD, DD, DD, 0);
    sgemm_nt<<<dim3(VV/128, TT/128), 256>>>(p_out, word_emb, p_log, nullptr, DD, DD, DD, VV, 0);
    row_logit_stats<<<TT, 256>>>(p_log, p_rmax, p_rsum);

    sgemm_nt<<<dim3(DD/128, TT/128), 256>>>(p_core, copy_w, p_copyh, copy_b, DD, DD, DD, DD, 0);
    bgemm_nt<<<dim3(EE/128, 1, BB), 256>>>(p_copyh, p_enct, p_IL, nullptr,
        DD, 1,
        DD, 0, BB*DD,
        DD, 0, BB*DD,
        EE, 0, BB*EE, 0);
    softmax_il<<<TT, 512>>>(p_IL, input_mask);
    mode_kernel<<<TT, 256>>>(p_core, mode_w, mode_b, p_msig);
    loss_kernel<<<1, 256>>>(p_log, p_rmax, p_rsum, p_msig, p_IL, input_ids, decode_target,
                            (float*)d_out);
}

// round 2
// speedup vs baseline: 1.8833x; 1.8833x over previous
#include <cuda_runtime.h>
#include <cuda_bf16.h>
#include <math.h>
#include <stdint.h>

// Problem dims
#define BB 8
#define SS 128
#define EE 512
#define DD 1024
#define HH 16
#define LL 4
#define VV 32000
#define DHH 64
#define FF_ 4096
#define TT (SS*BB)          // 1024 decoder tokens, row t = s*B + b
#define TE (EE*BB)          // 4096 encoder tokens, row t = e*B + b
#define SCALE_ 0.125f
#define NEG_ (-1e30f)

// ---------------- scratch (__device__ globals; no allocation allowed) ----------------
__device__ float g_r[SS*DD];
__device__ float g_rk[SS*DD];
__device__ float g_core[TT*DD];
__device__ float g_x[TT*DD];
__device__ float g_y[TT*DD];
__device__ float g_tmp[TT*DD];
__device__ float g_vec[TT*DD];
__device__ float g_q2[TT*DD];
__device__ float g_outb[TT*DD];
__device__ float g_copyh[TT*DD];
__device__ float g_enct[TE*DD];
__device__ float g_heads[TT*3*DD];
__device__ float g_kv[TE*2*DD];
__device__ float g_AC[BB*HH*SS*SS];
__device__ float g_BD[BB*HH*SS*SS];
__device__ float g_s2[BB*HH*SS*EE];
__device__ float g_h[TT*FF_];
__device__ float g_logits[(size_t)TT*VV];
__device__ float g_IL[TT*EE];
__device__ float g_rmax[TT];
__device__ float g_rsum[TT];
__device__ float g_msig[TT];

__device__ __forceinline__ uint32_t f2tf32(float x)
{
    uint32_t r;
    asm("cvt.rna.tf32.f32 %0, %1;" : "=r"(r) : "f"(x));
    return r;
}

// ---------------- tensor-core NT GEMM (tf32 mma.sync): C = A @ Bw^T (+bias,+gelu) ----
// A [M,K] row-major (lda), Bw [N,K] row-major (ldb). BM=BN=128, BK=32.
// 256 threads = 8 warps in 4(M) x 2(N); warp tile 32x64 = 2x8 mma tiles of 16x8.
__global__ __launch_bounds__(256, 2)
void sgemm_tc(const float* __restrict__ A, const float* __restrict__ Bw,
              float* __restrict__ C, const float* __restrict__ bias,
              int K, int lda, int ldb, int ldc, int act)
{
    __shared__ uint32_t As[32][136];   // [k][m], pad 136 -> conflict-free frag loads
    __shared__ uint32_t Bs[32][136];   // [k][n]

    int tid = threadIdx.x;
    int warp = tid >> 5, lane = tid & 31;
    int warp_m = warp >> 1;            // 0..3  (32 rows each)
    int warp_n = warp & 1;             // 0..1  (64 cols each)
    int rowA0 = blockIdx.y * 128;
    int colB0 = blockIdx.x * 128;

    int ldr = tid >> 1;                // 0..127 tile row for loads
    int ldk = (tid & 1) * 16;          // k chunk base (16 floats = 4 float4)

    int gid = lane >> 2;               // group id 0..7
    int tig = lane & 3;                // thread in group 0..3

    float c[2][8][4];
#pragma unroll
    for (int mi = 0; mi < 2; mi++)
#pragma unroll
        for (int ni = 0; ni < 8; ni++)
#pragma unroll
            for (int r = 0; r < 4; r++) c[mi][ni][r] = 0.f;

    for (int kb = 0; kb < K; kb += 32) {
        // load + convert A tile -> As[k][m]
        const float* Ap = &A[(size_t)(rowA0 + ldr) * lda + kb + ldk];
        const float* Bp = &Bw[(size_t)(colB0 + ldr) * ldb + kb + ldk];
#pragma unroll
        for (int j = 0; j < 4; j++) {
            float4 av = *reinterpret_cast<const float4*>(Ap + j * 4);
            As[ldk + j*4 + 0][ldr] = f2tf32(av.x);
            As[ldk + j*4 + 1][ldr] = f2tf32(av.y);
            As[ldk + j*4 + 2][ldr] = f2tf32(av.z);
            As[ldk + j*4 + 3][ldr] = f2tf32(av.w);
            float4 bv = *reinterpret_cast<const float4*>(Bp + j * 4);
            Bs[ldk + j*4 + 0][ldr] = f2tf32(bv.x);
            Bs[ldk + j*4 + 1][ldr] = f2tf32(bv.y);
            Bs[ldk + j*4 + 2][ldr] = f2tf32(bv.z);
            Bs[ldk + j*4 + 3][ldr] = f2tf32(bv.w);
        }
        __syncthreads();

#pragma unroll
        for (int ks = 0; ks < 4; ks++) {
            int k0 = ks * 8;
            uint32_t a[2][4];
#pragma unroll
            for (int mi = 0; mi < 2; mi++) {
                int rb = warp_m * 32 + mi * 16;
                a[mi][0] = As[k0 + tig    ][rb + gid    ];
                a[mi][1] = As[k0 + tig    ][rb + gid + 8];
                a[mi][2] = As[k0 + tig + 4][rb + gid    ];
                a[mi][3] = As[k0 + tig + 4][rb + gid + 8];
            }
            uint32_t b[8][2];
#pragma unroll
            for (int ni = 0; ni < 8; ni++) {
                int cb = warp_n * 64 + ni * 8;
                b[ni][0] = Bs[k0 + tig    ][cb + gid];
                b[ni][1] = Bs[k0 + tig + 4][cb + gid];
            }
#pragma unroll
            for (int mi = 0; mi < 2; mi++)
#pragma unroll
                for (int ni = 0; ni < 8; ni++) {
                    asm volatile(
                        "mma.sync.aligned.m16n8k8.row.col.f32.tf32.tf32.f32 "
                        "{%0,%1,%2,%3}, {%4,%5,%6,%7}, {%8,%9}, {%0,%1,%2,%3};\n"
                        : "+f"(c[mi][ni][0]), "+f"(c[mi][ni][1]),
                          "+f"(c[mi][ni][2]), "+f"(c[mi][ni][3])
                        : "r"(a[mi][0]), "r"(a[mi][1]), "r"(a[mi][2]), "r"(a[mi][3]),
                          "r"(b[ni][0]), "r"(b[ni][1]));
                }
        }
        __syncthreads();
    }

    // epilogue
#pragma unroll
    for (int mi = 0; mi < 2; mi++) {
        int row0 = rowA0 + warp_m * 32 + mi * 16 + gid;
#pragma unroll
        for (int ni = 0; ni < 8; ni++) {
            int col = colB0 + warp_n * 64 + ni * 8 + tig * 2;
#pragma unroll
            for (int half = 0; half < 2; half++) {
                int gm = row0 + half * 8;
                float v0 = c[mi][ni][half * 2 + 0];
                float v1 = c[mi][ni][half * 2 + 1];
                if (bias) { v0 += bias[col]; v1 += bias[col + 1]; }
                if (act == 1) {
                    v0 = 0.5f * v0 * (1.0f + erff(v0 * 0.70710678118654752f));
                    v1 = 0.5f * v1 * (1.0f + erff(v1 * 0.70710678118654752f));
                }
                C[(size_t)gm * ldc + col]     = v0;
                C[(size_t)gm * ldc + col + 1] = v1;
            }
        }
    }
}

// ---------------- batched NT gemm (M=128): C[i,n] = sum_k (A[i,k]+abias[k]) * B[n,k]
__global__ __launch_bounds__(256, 2)
void bgemm_nt(const float* __restrict__ A, const float* __restrict__ Bp,
              float* __restrict__ C, const float* __restrict__ abias,
              int K, int Hdim,
              long long aSB, long long aSH, int aRow,
              long long bSB, long long bSH, int bRow,
              long long cSB, long long cSH, int cRow, int abiasH)
{
    __shared__ float As[16][132];
    __shared__ float Bs[16][132];
    int z = blockIdx.z;
    int h = z % Hdim, b = z / Hdim;
    const float* Ab = A + (size_t)b * aSB + (size_t)h * aSH;
    const float* Bb = Bp + (size_t)b * bSB + (size_t)h * bSH;
    float* Cb = C + (size_t)b * cSB + (size_t)h * cSH;
    const float* biasb = abias ? (abias + (size_t)h * abiasH) : nullptr;

    int tid = threadIdx.x;
    int tx = tid & 15, ty = tid >> 4;
    int m0 = ty * 8, n0 = tx * 8;
    int colB0 = blockIdx.x * 128;
    int r  = tid >> 2;
    int c4 = (tid & 3) * 4;
    float acc[8][8];
#pragma unroll
    for (int i = 0; i < 8; i++)
#pragma unroll
        for (int j = 0; j < 8; j++) acc[i][j] = 0.f;

    for (int kb = 0; kb < K; kb += 16) {
        float4 biasv = make_float4(0.f, 0.f, 0.f, 0.f);
        if (biasb) biasv = *reinterpret_cast<const float4*>(&biasb[kb + c4]);
#pragma unroll
        for (int half = 0; half < 2; half++) {
            int rr = r + half * 64;
            float4 av = *reinterpret_cast<const float4*>(&Ab[(size_t)rr * aRow + kb + c4]);
            As[c4+0][rr] = av.x + biasv.x; As[c4+1][rr] = av.y + biasv.y;
            As[c4+2][rr] = av.z + biasv.z; As[c4+3][rr] = av.w + biasv.w;
            float4 bv = *reinterpret_cast<const float4*>(&Bb[(size_t)(colB0 + rr) * bRow + kb + c4]);
            Bs[c4+0][rr] = bv.x; Bs[c4+1][rr] = bv.y; Bs[c4+2][rr] = bv.z; Bs[c4+3][rr] = bv.w;
        }
        __syncthreads();
#pragma unroll
        for (int kk = 0; kk < 16; kk++) {
            float a[8], bb[8];
            *reinterpret_cast<float4*>(a)      = *reinterpret_cast<const float4*>(&As[kk][m0]);
            *reinterpret_cast<float4*>(a + 4)  = *reinterpret_cast<const float4*>(&As[kk][m0 + 4]);
            *reinterpret_cast<float4*>(bb)     = *reinterpret_cast<const float4*>(&Bs[kk][n0]);
            *reinterpret_cast<float4*>(bb + 4) = *reinterpret_cast<const float4*>(&Bs[kk][n0 + 4]);
#pragma unroll
            for (int i = 0; i < 8; i++)
#pragma unroll
                for (int j = 0; j < 8; j++) acc[i][j] += a[i] * bb[j];
        }
        __syncthreads();
    }
#pragma unroll
    for (int i = 0; i < 8; i++)
#pragma unroll
        for (int j = 0; j < 8; j++)
            Cb[(size_t)(m0 + i) * cRow + colB0 + n0 + j] = acc[i][j];
}

// ---------------- batched NN gemm (M=128, N=64): C[i,d] = sum_j A[i,j]*B[j,d] -------
__global__ __launch_bounds__(256, 2)
void bgemm_nn(const float* __restrict__ A, const float* __restrict__ Bp,
              float* __restrict__ C,
              int K, int Hdim,
              long long aSB, long long aSH, int aRow,
              long long bSB, long long bSH, int bRow,
              long long cSB, long long cSH, int cRow)
{
    __shared__ float As[16][132];
    __shared__ float Bs[16][68];
    int z = blockIdx.z;
    int h = z % Hdim, b = z / Hdim;
    const float* Ab = A + (size_t)b * aSB + (size_t)h * aSH;
    const float* Bb = Bp + (size_t)b * bSB + (size_t)h * bSH;
    float* Cb = C + (size_t)b * cSB + (size_t)h * cSH;

    int tid = threadIdx.x;
    int tx = tid & 15, ty = tid >> 4;
    int m0 = ty * 8, n0 = tx * 4;
    int rA = tid >> 2, c4A = (tid & 3) * 4;
    int rB = tid >> 4, c4B = (tid & 15) * 4;
    float acc[8][4];
#pragma unroll
    for (int i = 0; i < 8; i++)
#pragma unroll
        for (int j = 0; j < 4; j++) acc[i][j] = 0.f;

    for (int kb = 0; kb < K; kb += 16) {
#pragma unroll
        for (int half = 0; half < 2; half++) {
            int rr = rA + half * 64;
            float4 av = *reinterpret_cast<const float4*>(&Ab[(size_t)rr * aRow + kb + c4A]);
            As[c4A+0][rr] = av.x; As[c4A+1][rr] = av.y; As[c4A+2][rr] = av.z; As[c4A+3][rr] = av.w;
        }
        *reinterpret_cast<float4*>(&Bs[rB][c4B]) =
            *reinterpret_cast<const float4*>(&Bb[(size_t)(kb + rB) * bRow + c4B]);
        __syncthreads();
#pragma unroll
        for (int kk = 0; kk < 16; kk++) {
            float a[8], bb[4];
            *reinterpret_cast<float4*>(a)     = *reinterpret_cast<const float4*>(&As[kk][m0]);
            *reinterpret_cast<float4*>(a + 4) = *reinterpret_cast<const float4*>(&As[kk][m0 + 4]);
            *reinterpret_cast<float4*>(bb)    = *reinterpret_cast<const float4*>(&Bs[kk][n0]);
#pragma unroll
            for (int i = 0; i < 8; i++)
#pragma unroll
                for (int j = 0; j < 4; j++) acc[i][j] += a[i] * bb[j];
        }
        __syncthreads();
    }
#pragma unroll
    for (int i = 0; i < 8; i++)
#pragma unroll
        for (int j = 0; j < 4; j++)
            Cb[(size_t)(m0 + i) * cRow + n0 + j] = acc[i][j];
}

// ---------------- misc small kernels --------------------------------------------------
__global__ void pos_emb_kernel(float* __restrict__ r)
{
    int i = blockIdx.x;
    float pos = (float)(SS - 1 - i);
    const float LOG1E4 = 9.210340371976184f; // ln(10000)
    for (int d = threadIdx.x; d < DD; d += 256) {
        int j = (d < DD/2) ? d : d - DD/2;
        float invf = expf(-((float)j / (DD/2)) * LOG1E4);
        float a = pos * invf;
        r[i * DD + d] = (d < DD/2) ? sinf(a) : cosf(a);
    }
}

__global__ void embed_kernel(const int* __restrict__ dec, const float* __restrict__ emb,
                             float* __restrict__ core)
{
    int t = blockIdx.x;          // t = s*B + b
    int b = t & (BB-1), s = t >> 3;
    int id = dec[b * SS + s];
    const float* src = emb + (size_t)id * DD;
    float* dst = core + (size_t)t * DD;
    for (int d = threadIdx.x; d < DD; d += 256) dst[d] = src[d];
}

__global__ void transpose_enc(const float* __restrict__ enc, float* __restrict__ enct)
{
    int t = blockIdx.x;          // t = e*B + b
    int b = t & (BB-1), e = t >> 3;
    const float* src = enc + ((size_t)b * EE + e) * DD;
    float* dst = enct + (size_t)t * DD;
    for (int d = threadIdx.x; d < DD; d += 256) dst[d] = src[d];
}

// self-attn: score = (AC + relshift(BD))*SCALE, causal mask, softmax over j.
__global__ void softmax_self(const float* __restrict__ AC, const float* __restrict__ BD,
                             float* __restrict__ P)
{
    int row = blockIdx.x;        // (b*H+h)*S + i
    int i = row & (SS - 1);
    int bhBase = row - i;
    int j = threadIdx.x;         // 128
    float acv = AC[(size_t)row * SS + j];
    int f = i * SS + j + SS;
    int qi = f / (SS + 1), c = f % (SS + 1);
    float bd = (c > 0) ? BD[(size_t)(bhBase + qi) * SS + (c - 1)] : 0.0f;
    float s = (acv + bd) * SCALE_;
    if (j > i) s = NEG_;
    __shared__ float sh[128];
    sh[j] = s; __syncthreads();
    for (int st = 64; st > 0; st >>= 1) { if (j < st) sh[j] = fmaxf(sh[j], sh[j + st]); __syncthreads(); }
    float mx = sh[0]; __syncthreads();
    float e = expf(s - mx);
    sh[j] = e; __syncthreads();
    for (int st = 64; st > 0; st >>= 1) { if (j < st) sh[j] += sh[j + st]; __syncthreads(); }
    P[(size_t)row * SS + j] = e / sh[0];
}

// cross-attn: score*SCALE + (1-mask)*NEG, softmax over E. In-place.
__global__ void softmax_cross(float* __restrict__ S2, const float* __restrict__ mask)
{
    int row = blockIdx.x;        // (b*H+h)*S + i, 16384 rows
    int b = row / (HH * SS);
    int k = threadIdx.x;         // 512
    float v = S2[(size_t)row * EE + k] * SCALE_ + (1.0f - mask[b * EE + k]) * NEG_;
    __shared__ float sh[512];
    sh[k] = v; __syncthreads();
    for (int st = 256; st > 0; st >>= 1) { if (k < st) sh[k] = fmaxf(sh[k], sh[k + st]); __syncthreads(); }
    float mx = sh[0]; __syncthreads();
    float e = expf(v - mx);
    sh[k] = e; __syncthreads();
    for (int st = 256; st > 0; st >>= 1) { if (k < st) sh[k] += sh[k + st]; __syncthreads(); }
    S2[(size_t)row * EE + k] = e / sh[0];
}

// copy-attn softmax over E with mask, rows t=s*B+b. In-place.
__global__ void softmax_il(float* __restrict__ IL, const float* __restrict__ mask)
{
    int t = blockIdx.x;
    int b = t & (BB - 1);
    int k = threadIdx.x;         // 512
    float v = IL[(size_t)t * EE + k] + (1.0f - mask[b * EE + k]) * NEG_;
    __shared__ float sh[512];
    sh[k] = v; __syncthreads();
    for (int st = 256; st > 0; st >>= 1) { if (k < st) sh[k] = fmaxf(sh[k], sh[k + st]); __syncthreads(); }
    float mx = sh[0]; __syncthreads();
    float e = expf(v - mx);
    sh[k] = e; __syncthreads();
    for (int st = 256; st > 0; st >>= 1) { if (k < st) sh[k] += sh[k + st]; __syncthreads(); }
    IL[(size_t)t * EE + k] = e / sh[0];
}

// out = LayerNorm(resid + add) * g + b
__global__ void add_ln(const float* __restrict__ resid, const float* __restrict__ add,
                       float* __restrict__ out, const float* __restrict__ g,
                       const float* __restrict__ bta)
{
    int t = blockIdx.x;
    int tid = threadIdx.x;       // 256
    __shared__ float zb[DD];
    __shared__ float red[256];
    float s = 0.f;
#pragma unroll
    for (int u = 0; u < 4; u++) {
        int d = tid + u * 256;
        float z = resid[(size_t)t * DD + d] + add[(size_t)t * DD + d];
        zb[d] = z; s += z;
    }
    red[tid] = s; __syncthreads();
    for (int st = 128; st > 0; st >>= 1) { if (tid < st) red[tid] += red[tid + st]; __syncthreads(); }
    float mean = red[0] * (1.0f / DD); __syncthreads();
    float v = 0.f;
#pragma unroll
    for (int u = 0; u < 4; u++) {
        int d = tid + u * 256;
        float dz = zb[d] - mean; v += dz * dz;
    }
    red[tid] = v; __syncthreads();
    for (int st = 128; st > 0; st >>= 1) { if (tid < st) red[tid] += red[tid + st]; __syncthreads(); }
    float inv = rsqrtf(red[0] * (1.0f / DD) + 1e-5f);
#pragma unroll
    for (int u = 0; u < 4; u++) {
        int d = tid + u * 256;
        out[(size_t)t * DD + d] = (zb[d] - mean) * inv * g[d] + bta[d];
    }
}

__global__ void row_logit_stats(const float* __restrict__ Lg, float* __restrict__ rmax,
                                float* __restrict__ rsum)
{
    int t = blockIdx.x;
    int tid = threadIdx.x;       // 256
    const float* row = Lg + (size_t)t * VV;
    float m = -1e30f;
    for (int v = tid; v < VV; v += 256) m = fmaxf(m, row[v]);
    __shared__ float red[256];
    red[tid] = m; __syncthreads();
    for (int st = 128; st > 0; st >>= 1) { if (tid < st) red[tid] = fmaxf(red[tid], red[tid + st]); __syncthreads(); }
    m = red[0]; __syncthreads();
    float s = 0.f;
    for (int v = tid; v < VV; v += 256) s += expf(row[v] - m);
    red[tid] = s; __syncthreads();
    for (int st = 128; st > 0; st >>= 1) { if (tid < st) red[tid] += red[tid + st]; __syncthreads(); }
    if (tid == 0) { rmax[t] = m; rsum[t] = red[0]; }
}

__global__ void mode_kernel(const float* __restrict__ core, const float* __restrict__ mw,
                            const float* __restrict__ mb, float* __restrict__ msig)
{
    int t = blockIdx.x;
    int tid = threadIdx.x;       // 256
    float s = 0.f;
    for (int d = tid; d < DD; d += 256) s += core[(size_t)t * DD + d] * mw[d];
    __shared__ float red[256];
    red[tid] = s; __syncthreads();
    for (int st = 128; st > 0; st >>= 1) { if (tid < st) red[tid] += red[tid + st]; __syncthreads(); }
    if (tid == 0) msig[t] = 1.0f / (1.0f + expf(-(red[0] + mb[0])));
}

__global__ void loss_kernel(const float* __restrict__ logits, const float* __restrict__ rmax,
                            const float* __restrict__ rsum, const float* __restrict__ msig,
                            const float* __restrict__ IL, const int* __restrict__ input_ids,
                            const int* __restrict__ decode_target, float* __restrict__ out)
{
    int tid = threadIdx.x;       // 256
    float acc = 0.f, cnt = 0.f;
    for (int t = tid; t < TT; t += 256) {
        int b = t & (BB - 1), s = t >> 3;
        int tgt = decode_target[b * SS + s];
        if (tgt == 0) continue;
        float m = msig[t];
        float p = expf(logits[(size_t)t * VV + tgt] - rmax[t]) / rsum[t] * m;
        const int* ids = input_ids + b * EE;
        const float* il = IL + (size_t)t * EE;
        float cp = 0.f;
        for (int j = 0; j < EE; j++) if (ids[j] == tgt) cp += il[j];
        p += (1.0f - m) * cp;
        acc += -logf(p + 1e-6f);
        cnt += 1.0f;
    }
    __shared__ float sa[256], sc[256];
    sa[tid] = acc; sc[tid] = cnt; __syncthreads();
    for (int st = 128; st > 0; st >>= 1) {
        if (tid < st) { sa[tid] += sa[tid + st]; sc[tid] += sc[tid + st]; }
        __syncthreads();
    }
    if (tid < BB) out[tid] = sa[0] / sc[0];
}

// ---------------- host orchestration --------------------------------------------------
static float* symaddr(const void* sym)
{
    void* p = nullptr;
    cudaGetSymbolAddress(&p, sym);
    return (float*)p;
}

extern "C" void kernel_launch(void* const* d_in, const int* in_sizes, int n_in,
                              void* d_out, int out_size)
{
    const int*   input_ids     = (const int*)d_in[0];
    const float* encoder_rep   = (const float*)d_in[1];
    const float* input_mask    = (const float*)d_in[2];
    const int*   decode_input  = (const int*)d_in[3];
    const int*   decode_target = (const int*)d_in[4];
    const float* word_emb      = (const float*)d_in[5];
    const float* qkv_w         = (const float*)d_in[6];
    const float* r_w           = (const float*)d_in[7];
    const float* o_w           = (const float*)d_in[8];
    const float* kv_w          = (const float*)d_in[9];
    const float* q_w           = (const float*)d_in[10];
    const float* io_w          = (const float*)d_in[11];
    const float* rr_bias       = (const float*)d_in[12];
    const float* rw_bias       = (const float*)d_in[13];
    const float* ln1_g         = (const float*)d_in[14];
    const float* ln1_b         = (const float*)d_in[15];
    const float* ln2_g         = (const float*)d_in[16];
    const float* ln2_b         = (const float*)d_in[17];
    const float* ffn_w1        = (const float*)d_in[18];
    const float* ffn_b1        = (const float*)d_in[19];
    const float* ffn_w2        = (const float*)d_in[20];
    const float* ffn_b2        = (const float*)d_in[21];
    const float* ln3_g         = (const float*)d_in[22];
    const float* ln3_b         = (const float*)d_in[23];
    const float* out_w         = (const float*)d_in[24];
    const float* out_b         = (const float*)d_in[25];
    const float* copy_w        = (const float*)d_in[26];
    const float* copy_b        = (const float*)d_in[27];
    const float* mode_w        = (const float*)d_in[28];
    const float* mode_b        = (const float*)d_in[29];

    float* p_r     = symaddr(g_r);
    float* p_rk    = symaddr(g_rk);
    float* p_core  = symaddr(g_core);
    float* p_x     = symaddr(g_x);
    float* p_y     = symaddr(g_y);
    float* p_tmp   = symaddr(g_tmp);
    float* p_vec   = symaddr(g_vec);
    float* p_q2    = symaddr(g_q2);
    float* p_out   = symaddr(g_outb);
    float* p_copyh = symaddr(g_copyh);
    float* p_enct  = symaddr(g_enct);
    float* p_heads = symaddr(g_heads);
    float* p_kv    = symaddr(g_kv);
    float* p_AC    = symaddr(g_AC);
    float* p_BD    = symaddr(g_BD);
    float* p_s2    = symaddr(g_s2);
    float* p_h     = symaddr(g_h);
    float* p_log   = symaddr(g_logits);
    float* p_IL    = symaddr(g_IL);
    float* p_rmax  = symaddr(g_rmax);
    float* p_rsum  = symaddr(g_rsum);
    float* p_msig  = symaddr(g_msig);

    pos_emb_kernel<<<SS, 256>>>(p_r);
    embed_kernel<<<TT, 256>>>(decode_input, word_emb, p_core);
    transpose_enc<<<TE, 256>>>(encoder_rep, p_enct);

    for (int l = 0; l < LL; l++) {
        // heads = core @ qkv_w[l].T   [1024, 3072]
        sgemm_tc<<<dim3(3*DD/128, TT/128), 256>>>(p_core, qkv_w + (size_t)l*3*DD*DD, p_heads,
                                                  nullptr, DD, DD, DD, 3*DD, 0);
        // r_k = r @ r_w[l].T          [128, 1024]
        sgemm_tc<<<dim3(DD/128, SS/128), 256>>>(p_r, r_w + (size_t)l*DD*DD, p_rk,
                                                nullptr, DD, DD, DD, DD, 0);
        // AC[b,h,i,j] = (q + rw_bias) . k
        bgemm_nt<<<dim3(1, 1, BB*HH), 256>>>(p_heads, p_heads + DD, p_AC, rw_bias + (size_t)l*HH*DHH,
            DHH, HH,
            3*DD, DHH, BB*3*DD,
            3*DD, DHH, BB*3*DD,
            (long long)HH*SS*SS, (long long)SS*SS, SS, DHH);
        // BD[b,h,i,j] = (q + rr_bias) . r_k
        bgemm_nt<<<dim3(1, 1, BB*HH), 256>>>(p_heads, p_rk, p_BD, rr_bias + (size_t)l*HH*DHH,
            DHH, HH,
            3*DD, DHH, BB*3*DD,
            0, DHH, DD,
            (long long)HH*SS*SS, (long long)SS*SS, SS, DHH);
        softmax_self<<<BB*HH*SS, 128>>>(p_AC, p_BD, p_AC);
        // vec = prob @ v
        bgemm_nn<<<dim3(1, 1, BB*HH), 256>>>(p_AC, p_heads + 2*DD, p_vec,
            SS, HH,
            (long long)HH*SS*SS, (long long)SS*SS, SS,
            3*DD, DHH, BB*3*DD,
            DD, DHH, BB*DD);
        // x = LN(core + vec @ o_w.T)
        sgemm_tc<<<dim3(DD/128, TT/128), 256>>>(p_vec, o_w + (size_t)l*DD*DD, p_tmp,
                                                nullptr, DD, DD, DD, DD, 0);
        add_ln<<<TT, 256>>>(p_core, p_tmp, p_x, ln1_g + l*DD, ln1_b + l*DD);

        // cross attention
        sgemm_tc<<<dim3(2*DD/128, TE/128), 256>>>(p_enct, kv_w + (size_t)l*2*DD*DD, p_kv,
                                                  nullptr, DD, DD, DD, 2*DD, 0);
        sgemm_tc<<<dim3(DD/128, TT/128), 256>>>(p_x, q_w + (size_t)l*DD*DD, p_q2,
                                                nullptr, DD, DD, DD, DD, 0);
        bgemm_nt<<<dim3(EE/128, 1, BB*HH), 256>>>(p_q2, p_kv, p_s2, nullptr,
            DHH, HH,
            DD, DHH, BB*DD,
            2*DD, DHH, BB*2*DD,
            (long long)HH*SS*EE, (long long)SS*EE, EE, 0);
        softmax_cross<<<BB*HH*SS, 512>>>(p_s2, input_mask);
        bgemm_nn<<<dim3(1, 1, BB*HH), 256>>>(p_s2, p_kv + DD, p_vec,
            EE, HH,
            (long long)HH*SS*EE, (long long)SS*EE, EE,
            2*DD, DHH, BB*2*DD,
            DD, DHH, BB*DD);
        sgemm_tc<<<dim3(DD/128, TT/128), 256>>>(p_vec, io_w + (size_t)l*DD*DD, p_tmp,
                                                nullptr, DD, DD, DD, DD, 0);
        add_ln<<<TT, 256>>>(p_x, p_tmp, p_y, ln2_g + l*DD, ln2_b + l*DD);

        // FFN
        sgemm_tc<<<dim3(FF_/128, TT/128), 256>>>(p_y, ffn_w1 + (size_t)l*FF_*DD, p_h,
                                                 ffn_b1 + (size_t)l*FF_, DD, DD, DD, FF_, 1);
        sgemm_tc<<<dim3(DD/128, TT/128), 256>>>(p_h, ffn_w2 + (size_t)l*DD*FF_, p_tmp,
                                                ffn_b2 + (size_t)l*DD, FF_, FF_, FF_, DD, 0);
        add_ln<<<TT, 256>>>(p_y, p_tmp, p_core, ln3_g + l*DD, ln3_b + l*DD);
    }

    // output head
    sgemm_tc<<<dim3(DD/128, TT/128), 256>>>(p_core, out_w, p_out, out_b, DD, DD, DD, DD, 0);
    sgemm_tc<<<dim3(VV/128, TT/128), 256>>>(p_out, word_emb, p_log, nullptr, DD, DD, DD, VV, 0);
    row_logit_stats<<<TT, 256>>>(p_log, p_rmax, p_rsum);

    sgemm_tc<<<dim3(DD/128, TT/128), 256>>>(p_core, copy_w, p_copyh, copy_b, DD, DD, DD, DD, 0);
    bgemm_nt<<<dim3(EE/128, 1, BB), 256>>>(p_copyh, p_enct, p_IL, nullptr,
        DD, 1,
        DD, 0, BB*DD,
        DD, 0, BB*DD,
        EE, 0, BB*EE, 0);
    softmax_il<<<TT, 512>>>(p_IL, input_mask);
    mode_kernel<<<TT, 256>>>(p_core, mode_w, mode_b, p_msig);
    loss_kernel<<<1, 256>>>(p_log, p_rmax, p_rsum, p_msig, p_IL, input_ids, decode_target,
                            (float*)d_out);
}

// round 3
// speedup vs baseline: 3.2089x; 1.7038x over previous
#include <cuda_runtime.h>
#include <cuda_bf16.h>
#include <math.h>
#include <stdint.h>

// Problem dims
#define BB 8
#define SS 128
#define EE 512
#define DD 1024
#define HH 16
#define LL 4
#define VV 32000
#define DHH 64
#define FF_ 4096
#define TT (SS*BB)          // 1024 decoder tokens, row t = s*B + b
#define TE (EE*BB)          // 4096 encoder tokens, row t = e*B + b
#define SCALE_ 0.125f
#define NEG_ (-1e30f)

typedef __nv_bfloat16 bf16;

// ---------------- scratch (__device__ globals; no allocation allowed) ----------------
__device__ float g_r[SS*DD];
__device__ float g_rk[SS*DD];
__device__ float g_core[TT*DD];
__device__ float g_x[TT*DD];
__device__ float g_y[TT*DD];
__device__ float g_tmp[TT*DD];
__device__ float g_vec[TT*DD];
__device__ float g_q2[TT*DD];
__device__ float g_copyh[TT*DD];
__device__ float g_enct[TE*DD];
__device__ float g_heads[TT*3*DD];
__device__ float g_kv[TE*2*DD];
__device__ float g_AC[BB*HH*SS*SS];
__device__ float g_BD[BB*HH*SS*SS];
__device__ float g_s2[BB*HH*SS*EE];
__device__ float g_logits[(size_t)TT*VV];
__device__ float g_IL[TT*EE];
__device__ float g_rmax[TT];
__device__ float g_rsum[TT];
__device__ float g_msig[TT];

// bf16 activations
__device__ bf16 b_core[TT*DD];
__device__ bf16 b_r[SS*DD];
__device__ bf16 b_x[TT*DD];
__device__ bf16 b_y[TT*DD];
__device__ bf16 b_vec[TT*DD];
__device__ bf16 b_enct[TE*DD];
__device__ bf16 b_h[TT*FF_];
__device__ bf16 b_outb[TT*DD];

// bf16 weights
__device__ bf16 w_qkv[LL*3*DD*DD];
__device__ bf16 w_r[LL*DD*DD];
__device__ bf16 w_o[LL*DD*DD];
__device__ bf16 w_kv[LL*2*DD*DD];
__device__ bf16 w_q[LL*DD*DD];
__device__ bf16 w_io[LL*DD*DD];
__device__ bf16 w_f1[LL*FF_*DD];
__device__ bf16 w_f2[LL*DD*FF_];
__device__ bf16 w_emb[(size_t)VV*DD];
__device__ bf16 w_out[DD*DD];
__device__ bf16 w_copy[DD*DD];

__device__ __forceinline__ uint32_t smem_u32(const void* p)
{
    return (uint32_t)__cvta_generic_to_shared(p);
}

// ---------------- f32 -> bf16 conversion (vectorized) --------------------------------
__global__ void cvt_bf16(const float* __restrict__ src, bf16* __restrict__ dst, int n)
{
    int i = (blockIdx.x * 256 + threadIdx.x) * 4;
    if (i >= n) return;
    float4 v = *reinterpret_cast<const float4*>(src + i);
    uint32_t lo = ((uint32_t)__bfloat16_as_ushort(__float2bfloat16_rn(v.y)) << 16)
                | (uint32_t)__bfloat16_as_ushort(__float2bfloat16_rn(v.x));
    uint32_t hi = ((uint32_t)__bfloat16_as_ushort(__float2bfloat16_rn(v.w)) << 16)
                | (uint32_t)__bfloat16_as_ushort(__float2bfloat16_rn(v.z));
    uint2 u = make_uint2(lo, hi);
    *reinterpret_cast<uint2*>(dst + i) = u;
}

// ---------------- bf16 tensor-core NT GEMM: C = A @ Bw^T (+bias, +gelu) --------------
// A [M,K] bf16 row-major (lda), Bw [N,K] bf16 row-major (ldb).
// BM=BN=128, BK=32, 256 threads = 8 warps in 4(M) x 2(N); warp tile 32x64.
// mma m16n8k16, ldmatrix.x4 fragments, 2-stage cp.async pipeline.
__global__ __launch_bounds__(256, 2)
void sgemm_bf(const bf16* __restrict__ A, const bf16* __restrict__ Bw,
              float* __restrict__ Cf, bf16* __restrict__ Cb,
              const float* __restrict__ bias,
              int K, int lda, int ldb, int ldc, int act)
{
    __shared__ bf16 As[2][128][40];
    __shared__ bf16 Bs[2][128][40];

    int tid = threadIdx.x;
    int warp = tid >> 5, lane = tid & 31;
    int warp_m = warp >> 1;            // 0..3
    int warp_n = warp & 1;             // 0..1
    int rowA0 = blockIdx.y * 128;
    int colB0 = blockIdx.x * 128;

    int ldrow = tid >> 1;              // 0..127
    int ldkoff = (tid & 1) * 16;       // 0 or 16

    float c[2][8][4];
#pragma unroll
    for (int mi = 0; mi < 2; mi++)
#pragma unroll
        for (int ni = 0; ni < 8; ni++)
#pragma unroll
            for (int r = 0; r < 4; r++) c[mi][ni][r] = 0.f;

    const bf16* Agp = &A[(size_t)(rowA0 + ldrow) * lda + ldkoff];
    const bf16* Bgp = &Bw[(size_t)(colB0 + ldrow) * ldb + ldkoff];

    // prologue: stage 0
    {
        uint32_t sa = smem_u32(&As[0][ldrow][ldkoff]);
        uint32_t sb = smem_u32(&Bs[0][ldrow][ldkoff]);
        asm volatile("cp.async.ca.shared.global [%0], [%1], 16;\n"
                     "cp.async.ca.shared.global [%2], [%3], 16;\n"
                     "cp.async.ca.shared.global [%4], [%5], 16;\n"
                     "cp.async.ca.shared.global [%6], [%7], 16;\n"
                     :: "r"(sa), "l"(Agp), "r"(sa + 16), "l"(Agp + 8),
                        "r"(sb), "l"(Bgp), "r"(sb + 16), "l"(Bgp + 8));
        asm volatile("cp.async.commit_group;");
    }

    int buf = 0;
    for (int kb = 0; kb < K; kb += 32) {
        asm volatile("cp.async.wait_group 0;");
        __syncthreads();
        if (kb + 32 < K) {
            int nb = buf ^ 1;
            uint32_t sa = smem_u32(&As[nb][ldrow][ldkoff]);
            uint32_t sb = smem_u32(&Bs[nb][ldrow][ldkoff]);
            const bf16* ag = Agp + kb + 32;
            const bf16* bg = Bgp + kb + 32;
            asm volatile("cp.async.ca.shared.global [%0], [%1], 16;\n"
                         "cp.async.ca.shared.global [%2], [%3], 16;\n"
                         "cp.async.ca.shared.global [%4], [%5], 16;\n"
                         "cp.async.ca.shared.global [%6], [%7], 16;\n"
                         :: "r"(sa), "l"(ag), "r"(sa + 16), "l"(ag + 8),
                            "r"(sb), "l"(bg), "r"(sb + 16), "l"(bg + 8));
            asm volatile("cp.async.commit_group;");
        }

#pragma unroll
        for (int ks = 0; ks < 2; ks++) {
            int k0 = ks * 16;
            // A fragments: 2 ldmatrix.x4
            uint32_t a[2][4];
#pragma unroll
            for (int mi = 0; mi < 2; mi++) {
                int m = warp_m * 32 + mi * 16 + (lane & 15);
                int kc = k0 + ((lane >> 4) << 3);
                uint32_t addr = smem_u32(&As[buf][m][kc]);
                asm volatile("ldmatrix.sync.aligned.m8n8.x4.shared.b16 {%0,%1,%2,%3}, [%4];"
                             : "=r"(a[mi][0]), "=r"(a[mi][1]), "=r"(a[mi][2]), "=r"(a[mi][3])
                             : "r"(addr));
            }
            // B fragments: 4 ldmatrix.x4 (each covers 2 n-tiles)
            uint32_t b[8][2];
#pragma unroll
            for (int nt = 0; nt < 4; nt++) {
                int n = warp_n * 64 + nt * 16 + (lane & 7) + ((lane >> 4) << 3);
                int kc = k0 + (((lane >> 3) & 1) << 3);
                uint32_t addr = smem_u32(&Bs[buf][n][kc]);
                asm volatile("ldmatrix.sync.aligned.m8n8.x4.shared.b16 {%0,%1,%2,%3}, [%4];"
                             : "=r"(b[nt*2][0]), "=r"(b[nt*2][1]),
                               "=r"(b[nt*2+1][0]), "=r"(b[nt*2+1][1])
                             : "r"(addr));
            }
#pragma unroll
            for (int mi = 0; mi < 2; mi++)
#pragma unroll
                for (int ni = 0; ni < 8; ni++) {
                    asm volatile(
                        "mma.sync.aligned.m16n8k16.row.col.f32.bf16.bf16.f32 "
                        "{%0,%1,%2,%3}, {%4,%5,%6,%7}, {%8,%9}, {%0,%1,%2,%3};\n"
                        : "+f"(c[mi][ni][0]), "+f"(c[mi][ni][1]),
                          "+f"(c[mi][ni][2]), "+f"(c[mi][ni][3])
                        : "r"(a[mi][0]), "r"(a[mi][1]), "r"(a[mi][2]), "r"(a[mi][3]),
                          "r"(b[ni][0]), "r"(b[ni][1]));
                }
        }
        buf ^= 1;
        __syncthreads();
    }

    // epilogue
#pragma unroll
    for (int mi = 0; mi < 2; mi++) {
        int row0 = rowA0 + warp_m * 32 + mi * 16 + (lane >> 2);
#pragma unroll
        for (int ni = 0; ni < 8; ni++) {
            int col = colB0 + warp_n * 64 + ni * 8 + (lane & 3) * 2;
            float bv0 = 0.f, bv1 = 0.f;
            if (bias) { bv0 = bias[col]; bv1 = bias[col + 1]; }
#pragma unroll
            for (int half = 0; half < 2; half++) {
                int gm = row0 + half * 8;
                float v0 = c[mi][ni][half * 2 + 0] + bv0;
                float v1 = c[mi][ni][half * 2 + 1] + bv1;
                if (act == 1) {
                    v0 = 0.5f * v0 * (1.0f + erff(v0 * 0.70710678118654752f));
                    v1 = 0.5f * v1 * (1.0f + erff(v1 * 0.70710678118654752f));
                }
                if (Cf) {
                    Cf[(size_t)gm * ldc + col]     = v0;
                    Cf[(size_t)gm * ldc + col + 1] = v1;
                }
                if (Cb) {
                    uint32_t pk = ((uint32_t)__bfloat16_as_ushort(__float2bfloat16_rn(v1)) << 16)
                                | (uint32_t)__bfloat16_as_ushort(__float2bfloat16_rn(v0));
                    *reinterpret_cast<uint32_t*>(&Cb[(size_t)gm * ldc + col]) = pk;
                }
            }
        }
    }
}

// ---------------- batched NT gemm (M=128): C[i,n] = sum_k (A[i,k]+abias[k]) * B[n,k]
__global__ __launch_bounds__(256, 2)
void bgemm_nt(const float* __restrict__ A, const float* __restrict__ Bp,
              float* __restrict__ C, const float* __restrict__ abias,
              int K, int Hdim,
              long long aSB, long long aSH, int aRow,
              long long bSB, long long bSH, int bRow,
              long long cSB, long long cSH, int cRow, int abiasH)
{
    __shared__ float As[16][132];
    __shared__ float Bs[16][132];
    int z = blockIdx.z;
    int h = z % Hdim, b = z / Hdim;
    const float* Ab = A + (size_t)b * aSB + (size_t)h * aSH;
    const float* Bb = Bp + (size_t)b * bSB + (size_t)h * bSH;
    float* Cb = C + (size_t)b * cSB + (size_t)h * cSH;
    const float* biasb = abias ? (abias + (size_t)h * abiasH) : nullptr;

    int tid = threadIdx.x;
    int tx = tid & 15, ty = tid >> 4;
    int m0 = ty * 8, n0 = tx * 8;
    int colB0 = blockIdx.x * 128;
    int r  = tid >> 2;
    int c4 = (tid & 3) * 4;
    float acc[8][8];
#pragma unroll
    for (int i = 0; i < 8; i++)
#pragma unroll
        for (int j = 0; j < 8; j++) acc[i][j] = 0.f;

    for (int kb = 0; kb < K; kb += 16) {
        float4 biasv = make_float4(0.f, 0.f, 0.f, 0.f);
        if (biasb) biasv = *reinterpret_cast<const float4*>(&biasb[kb + c4]);
#pragma unroll
        for (int half = 0; half < 2; half++) {
            int rr = r + half * 64;
            float4 av = *reinterpret_cast<const float4*>(&Ab[(size_t)rr * aRow + kb + c4]);
            As[c4+0][rr] = av.x + biasv.x; As[c4+1][rr] = av.y + biasv.y;
            As[c4+2][rr] = av.z + biasv.z; As[c4+3][rr] = av.w + biasv.w;
            float4 bv = *reinterpret_cast<const float4*>(&Bb[(size_t)(colB0 + rr) * bRow + kb + c4]);
            Bs[c4+0][rr] = bv.x; Bs[c4+1][rr] = bv.y; Bs[c4+2][rr] = bv.z; Bs[c4+3][rr] = bv.w;
        }
        __syncthreads();
#pragma unroll
        for (int kk = 0; kk < 16; kk++) {
            float a[8], bb[8];
            *reinterpret_cast<float4*>(a)      = *reinterpret_cast<const float4*>(&As[kk][m0]);
            *reinterpret_cast<float4*>(a + 4)  = *reinterpret_cast<const float4*>(&As[kk][m0 + 4]);
            *reinterpret_cast<float4*>(bb)     = *reinterpret_cast<const float4*>(&Bs[kk][n0]);
            *reinterpret_cast<float4*>(bb + 4) = *reinterpret_cast<const float4*>(&Bs[kk][n0 + 4]);
#pragma unroll
            for (int i = 0; i < 8; i++)
#pragma unroll
                for (int j = 0; j < 8; j++) acc[i][j] += a[i] * bb[j];
        }
        __syncthreads();
    }
#pragma unroll
    for (int i = 0; i < 8; i++)
#pragma unroll
        for (int j = 0; j < 8; j++)
            Cb[(size_t)(m0 + i) * cRow + colB0 + n0 + j] = acc[i][j];
}

// ---------------- batched NN gemm (M=128, N=64): C[i,d] = sum_j A[i,j]*B[j,d] -------
// Also writes bf16 copy if Cbf != null.
__global__ __launch_bounds__(256, 2)
void bgemm_nn(const float* __restrict__ A, const float* __restrict__ Bp,
              float* __restrict__ C, bf16* __restrict__ Cbf,
              int K, int Hdim,
              long long aSB, long long aSH, int aRow,
              long long bSB, long long bSH, int bRow,
              long long cSB, long long cSH, int cRow)
{
    __shared__ float As[16][132];
    __shared__ float Bs[16][68];
    int z = blockIdx.z;
    int h = z % Hdim, b = z / Hdim;
    const float* Ab = A + (size_t)b * aSB + (size_t)h * aSH;
    const float* Bb = Bp + (size_t)b * bSB + (size_t)h * bSH;
    float* Cb = C + (size_t)b * cSB + (size_t)h * cSH;
    bf16* Cb2 = Cbf ? (Cbf + (size_t)b * cSB + (size_t)h * cSH) : nullptr;

    int tid = threadIdx.x;
    int tx = tid & 15, ty = tid >> 4;
    int m0 = ty * 8, n0 = tx * 4;
    int rA = tid >> 2, c4A = (tid & 3) * 4;
    int rB = tid >> 4, c4B = (tid & 15) * 4;
    float acc[8][4];
#pragma unroll
    for (int i = 0; i < 8; i++)
#pragma unroll
        for (int j = 0; j < 4; j++) acc[i][j] = 0.f;

    for (int kb = 0; kb < K; kb += 16) {
#pragma unroll
        for (int half = 0; half < 2; half++) {
            int rr = rA + half * 64;
            float4 av = *reinterpret_cast<const float4*>(&Ab[(size_t)rr * aRow + kb + c4A]);
            As[c4A+0][rr] = av.x; As[c4A+1][rr] = av.y; As[c4A+2][rr] = av.z; As[c4A+3][rr] = av.w;
        }
        *reinterpret_cast<float4*>(&Bs[rB][c4B]) =
            *reinterpret_cast<const float4*>(&Bb[(size_t)(kb + rB) * bRow + c4B]);
        __syncthreads();
#pragma unroll
        for (int kk = 0; kk < 16; kk++) {
            float a[8], bb[4];
            *reinterpret_cast<float4*>(a)     = *reinterpret_cast<const float4*>(&As[kk][m0]);
            *reinterpret_cast<float4*>(a + 4) = *reinterpret_cast<const float4*>(&As[kk][m0 + 4]);
            *reinterpret_cast<float4*>(bb)    = *reinterpret_cast<const float4*>(&Bs[kk][n0]);
#pragma unroll
            for (int i = 0; i < 8; i++)
#pragma unroll
                for (int j = 0; j < 4; j++) acc[i][j] += a[i] * bb[j];
        }
        __syncthreads();
    }
#pragma unroll
    for (int i = 0; i < 8; i++)
#pragma unroll
        for (int j = 0; j < 4; j++) {
            float v = acc[i][j];
            Cb[(size_t)(m0 + i) * cRow + n0 + j] = v;
            if (Cb2) Cb2[(size_t)(m0 + i) * cRow + n0 + j] = __float2bfloat16_rn(v);
        }
}

// ---------------- misc small kernels --------------------------------------------------
__global__ void pos_emb_kernel(float* __restrict__ r, bf16* __restrict__ rb)
{
    int i = blockIdx.x;
    float pos = (float)(SS - 1 - i);
    const float LOG1E4 = 9.210340371976184f;
    for (int d = threadIdx.x; d < DD; d += 256) {
        int j = (d < DD/2) ? d : d - DD/2;
        float invf = expf(-((float)j / (DD/2)) * LOG1E4);
        float a = pos * invf;
        float v = (d < DD/2) ? sinf(a) : cosf(a);
        r[i * DD + d] = v;
        rb[i * DD + d] = __float2bfloat16_rn(v);
    }
}

__global__ void embed_kernel(const int* __restrict__ dec, const float* __restrict__ emb,
                             float* __restrict__ core, bf16* __restrict__ coreb)
{
    int t = blockIdx.x;
    int b = t & (BB-1), s = t >> 3;
    int id = dec[b * SS + s];
    const float* src = emb + (size_t)id * DD;
    for (int d = threadIdx.x; d < DD; d += 256) {
        float v = src[d];
        core[(size_t)t * DD + d] = v;
        coreb[(size_t)t * DD + d] = __float2bfloat16_rn(v);
    }
}

__global__ void transpose_enc(const float* __restrict__ enc, float* __restrict__ enct,
                              bf16* __restrict__ enctb)
{
    int t = blockIdx.x;
    int b = t & (BB-1), e = t >> 3;
    const float* src = enc + ((size_t)b * EE + e) * DD;
    for (int d = threadIdx.x; d < DD; d += 256) {
        float v = src[d];
        enct[(size_t)t * DD + d] = v;
        enctb[(size_t)t * DD + d] = __float2bfloat16_rn(v);
    }
}

// self-attn: score = (AC + relshift(BD))*SCALE, causal mask, softmax over j.
__global__ void softmax_self(const float* __restrict__ AC, const float* __restrict__ BD,
                             float* __restrict__ P)
{
    int row = blockIdx.x;
    int i = row & (SS - 1);
    int bhBase = row - i;
    int j = threadIdx.x;
    float acv = AC[(size_t)row * SS + j];
    int f = i * SS + j + SS;
    int qi = f / (SS + 1), c = f % (SS + 1);
    float bd = (c > 0) ? BD[(size_t)(bhBase + qi) * SS + (c - 1)] : 0.0f;
    float s = (acv + bd) * SCALE_;
    if (j > i) s = NEG_;
    __shared__ float sh[128];
    sh[j] = s; __syncthreads();
    for (int st = 64; st > 0; st >>= 1) { if (j < st) sh[j] = fmaxf(sh[j], sh[j + st]); __syncthreads(); }
    float mx = sh[0]; __syncthreads();
    float e = expf(s - mx);
    sh[j] = e; __syncthreads();
    for (int st = 64; st > 0; st >>= 1) { if (j < st) sh[j] += sh[j + st]; __syncthreads(); }
    P[(size_t)row * SS + j] = e / sh[0];
}

__global__ void softmax_cross(float* __restrict__ S2, const float* __restrict__ mask)
{
    int row = blockIdx.x;
    int b = row / (HH * SS);
    int k = threadIdx.x;
    float v = S2[(size_t)row * EE + k] * SCALE_ + (1.0f - mask[b * EE + k]) * NEG_;
    __shared__ float sh[512];
    sh[k] = v; __syncthreads();
    for (int st = 256; st > 0; st >>= 1) { if (k < st) sh[k] = fmaxf(sh[k], sh[k + st]); __syncthreads(); }
    float mx = sh[0]; __syncthreads();
    float e = expf(v - mx);
    sh[k] = e; __syncthreads();
    for (int st = 256; st > 0; st >>= 1) { if (k < st) sh[k] += sh[k + st]; __syncthreads(); }
    S2[(size_t)row * EE + k] = e / sh[0];
}

__global__ void softmax_il(float* __restrict__ IL, const float* __restrict__ mask)
{
    int t = blockIdx.x;
    int b = t & (BB - 1);
    int k = threadIdx.x;
    float v = IL[(size_t)t * EE + k] + (1.0f - mask[b * EE + k]) * NEG_;
    __shared__ float sh[512];
    sh[k] = v; __syncthreads();
    for (int st = 256; st > 0; st >>= 1) { if (k < st) sh[k] = fmaxf(sh[k], sh[k + st]); __syncthreads(); }
    float mx = sh[0]; __syncthreads();
    float e = expf(v - mx);
    sh[k] = e; __syncthreads();
    for (int st = 256; st > 0; st >>= 1) { if (k < st) sh[k] += sh[k + st]; __syncthreads(); }
    IL[(size_t)t * EE + k] = e / sh[0];
}

// out = LayerNorm(resid + add); writes f32 and optional bf16
__global__ void add_ln(const float* __restrict__ resid, const float* __restrict__ add,
                       float* __restrict__ out, bf16* __restrict__ outb,
                       const float* __restrict__ g, const float* __restrict__ bta)
{
    int t = blockIdx.x;
    int tid = threadIdx.x;
    __shared__ float zb[DD];
    __shared__ float red[256];
    float s = 0.f;
#pragma unroll
    for (int u = 0; u < 4; u++) {
        int d = tid + u * 256;
        float z = resid[(size_t)t * DD + d] + add[(size_t)t * DD + d];
        zb[d] = z; s += z;
    }
    red[tid] = s; __syncthreads();
    for (int st = 128; st > 0; st >>= 1) { if (tid < st) red[tid] += red[tid + st]; __syncthreads(); }
    float mean = red[0] * (1.0f / DD); __syncthreads();
    float v = 0.f;
#pragma unroll
    for (int u = 0; u < 4; u++) {
        int d = tid + u * 256;
        float dz = zb[d] - mean; v += dz * dz;
    }
    red[tid] = v; __syncthreads();
    for (int st = 128; st > 0; st >>= 1) { if (tid < st) red[tid] += red[tid + st]; __syncthreads(); }
    float inv = rsqrtf(red[0] * (1.0f / DD) + 1e-5f);
#pragma unroll
    for (int u = 0; u < 4; u++) {
        int d = tid + u * 256;
        float o = (zb[d] - mean) * inv * g[d] + bta[d];
        out[(size_t)t * DD + d] = o;
        if (outb) outb[(size_t)t * DD + d] = __float2bfloat16_rn(o);
    }
}

__global__ void row_logit_stats(const float* __restrict__ Lg, float* __restrict__ rmax,
                                float* __restrict__ rsum)
{
    int t = blockIdx.x;
    int tid = threadIdx.x;
    const float* row = Lg + (size_t)t * VV;
    float m = -1e30f;
    for (int v = tid; v < VV; v += 256) m = fmaxf(m, row[v]);
    __shared__ float red[256];
    red[tid] = m; __syncthreads();
    for (int st = 128; st > 0; st >>= 1) { if (tid < st) red[tid] = fmaxf(red[tid], red[tid + st]); __syncthreads(); }
    m = red[0]; __syncthreads();
    float s = 0.f;
    for (int v = tid; v < VV; v += 256) s += expf(row[v] - m);
    red[tid] = s; __syncthreads();
    for (int st = 128; st > 0; st >>= 1) { if (tid < st) red[tid] += red[tid + st]; __syncthreads(); }
    if (tid == 0) { rmax[t] = m; rsum[t] = red[0]; }
}

__global__ void mode_kernel(const float* __restrict__ core, const float* __restrict__ mw,
                            const float* __restrict__ mb, float* __restrict__ msig)
{
    int t = blockIdx.x;
    int tid = threadIdx.x;
    float s = 0.f;
    for (int d = tid; d < DD; d += 256) s += core[(size_t)t * DD + d] * mw[d];
    __shared__ float red[256];
    red[tid] = s; __syncthreads();
    for (int st = 128; st > 0; st >>= 1) { if (tid < st) red[tid] += red[tid + st]; __syncthreads(); }
    if (tid == 0) msig[t] = 1.0f / (1.0f + expf(-(red[0] + mb[0])));
}

__global__ void loss_kernel(const float* __restrict__ logits, const float* __restrict__ rmax,
                            const float* __restrict__ rsum, const float* __restrict__ msig,
                            const float* __restrict__ IL, const int* __restrict__ input_ids,
                            const int* __restrict__ decode_target, float* __restrict__ out)
{
    int tid = threadIdx.x;
    float acc = 0.f, cnt = 0.f;
    for (int t = tid; t < TT; t += 256) {
        int b = t & (BB - 1), s = t >> 3;
        int tgt = decode_target[b * SS + s];
        if (tgt == 0) continue;
        float m = msig[t];
        float p = expf(logits[(size_t)t * VV + tgt] - rmax[t]) / rsum[t] * m;
        const int* ids = input_ids + b * EE;
        const float* il = IL + (size_t)t * EE;
        float cp = 0.f;
        for (int j = 0; j < EE; j++) if (ids[j] == tgt) cp += il[j];
        p += (1.0f - m) * cp;
        acc += -logf(p + 1e-6f);
        cnt += 1.0f;
    }
    __shared__ float sa[256], sc[256];
    sa[tid] = acc; sc[tid] = cnt; __syncthreads();
    for (int st = 128; st > 0; st >>= 1) {
        if (tid < st) { sa[tid] += sa[tid + st]; sc[tid] += sc[tid + st]; }
        __syncthreads();
    }
    if (tid < BB) out[tid] = sa[0] / sc[0];
}

// ---------------- host orchestration --------------------------------------------------
static void* symaddr(const void* sym)
{
    void* p = nullptr;
    cudaGetSymbolAddress(&p, sym);
    return p;
}

static void cvt(const float* src, bf16* dst, size_t n)
{
    int blocks = (int)((n / 4 + 255) / 256);
    cvt_bf16<<<blocks, 256>>>(src, dst, (int)n);
}

extern "C" void kernel_launch(void* const* d_in, const int* in_sizes, int n_in,
                              void* d_out, int out_size)
{
    const int*   input_ids     = (const int*)d_in[0];
    const float* encoder_rep   = (const float*)d_in[1];
    const float* input_mask    = (const float*)d_in[2];
    const int*   decode_input  = (const int*)d_in[3];
    const int*   decode_target = (const int*)d_in[4];
    const float* word_emb      = (const float*)d_in[5];
    const float* qkv_w         = (const float*)d_in[6];
    const float* r_w           = (const float*)d_in[7];
    const float* o_w           = (const float*)d_in[8];
    const float* kv_w          = (const float*)d_in[9];
    const float* q_w           = (const float*)d_in[10];
    const float* io_w          = (const float*)d_in[11];
    const float* rr_bias       = (const float*)d_in[12];
    const float* rw_bias       = (const float*)d_in[13];
    const float* ln1_g         = (const float*)d_in[14];
    const float* ln1_b         = (const float*)d_in[15];
    const float* ln2_g         = (const float*)d_in[16];
    const float* ln2_b         = (const float*)d_in[17];
    const float* ffn_w1        = (const float*)d_in[18];
    const float* ffn_b1        = (const float*)d_in[19];
    const float* ffn_w2        = (const float*)d_in[20];
    const float* ffn_b2        = (const float*)d_in[21];
    const float* ln3_g         = (const float*)d_in[22];
    const float* ln3_b         = (const float*)d_in[23];
    const float* out_w         = (const float*)d_in[24];
    const float* out_b         = (const float*)d_in[25];
    const float* copy_w        = (const float*)d_in[26];
    const float* copy_b        = (const float*)d_in[27];
    const float* mode_w        = (const float*)d_in[28];
    const float* mode_b        = (const float*)d_in[29];

    float* p_r     = (float*)symaddr(g_r);
    float* p_rk    = (float*)symaddr(g_rk);
    float* p_core  = (float*)symaddr(g_core);
    float* p_x     = (float*)symaddr(g_x);
    float* p_y     = (float*)symaddr(g_y);
    float* p_tmp   = (float*)symaddr(g_tmp);
    float* p_vec   = (float*)symaddr(g_vec);
    float* p_q2    = (float*)symaddr(g_q2);
    float* p_copyh = (float*)symaddr(g_copyh);
    float* p_enct  = (float*)symaddr(g_enct);
    float* p_heads = (float*)symaddr(g_heads);
    float* p_kv    = (float*)symaddr(g_kv);
    float* p_AC    = (float*)symaddr(g_AC);
    float* p_BD    = (float*)symaddr(g_BD);
    float* p_s2    = (float*)symaddr(g_s2);
    float* p_log   = (float*)symaddr(g_logits);
    float* p_IL    = (float*)symaddr(g_IL);
    float* p_rmax  = (float*)symaddr(g_rmax);
    float* p_rsum  = (float*)symaddr(g_rsum);
    float* p_msig  = (float*)symaddr(g_msig);

    bf16* pb_core = (bf16*)symaddr(b_core);
    bf16* pb_r    = (bf16*)symaddr(b_r);
    bf16* pb_x    = (bf16*)symaddr(b_x);
    bf16* pb_y    = (bf16*)symaddr(b_y);
    bf16* pb_vec  = (bf16*)symaddr(b_vec);
    bf16* pb_enct = (bf16*)symaddr(b_enct);
    bf16* pb_h    = (bf16*)symaddr(b_h);
    bf16* pb_outb = (bf16*)symaddr(b_outb);

    bf16* pw_qkv = (bf16*)symaddr(w_qkv);
    bf16* pw_r   = (bf16*)symaddr(w_r);
    bf16* pw_o   = (bf16*)symaddr(w_o);
    bf16* pw_kv  = (bf16*)symaddr(w_kv);
    bf16* pw_q   = (bf16*)symaddr(w_q);
    bf16* pw_io  = (bf16*)symaddr(w_io);
    bf16* pw_f1  = (bf16*)symaddr(w_f1);
    bf16* pw_f2  = (bf16*)symaddr(w_f2);
    bf16* pw_emb = (bf16*)symaddr(w_emb);
    bf16* pw_out = (bf16*)symaddr(w_out);
    bf16* pw_cp  = (bf16*)symaddr(w_copy);

    // one-time weight conversions (part of the captured graph)
    cvt(qkv_w,  pw_qkv, (size_t)LL*3*DD*DD);
    cvt(r_w,    pw_r,   (size_t)LL*DD*DD);
    cvt(o_w,    pw_o,   (size_t)LL*DD*DD);
    cvt(kv_w,   pw_kv,  (size_t)LL*2*DD*DD);
    cvt(q_w,    pw_q,   (size_t)LL*DD*DD);
    cvt(io_w,   pw_io,  (size_t)LL*DD*DD);
    cvt(ffn_w1, pw_f1,  (size_t)LL*FF_*DD);
    cvt(ffn_w2, pw_f2,  (size_t)LL*DD*FF_);
    cvt(word_emb, pw_emb, (size_t)VV*DD);
    cvt(out_w,  pw_out, (size_t)DD*DD);
    cvt(copy_w, pw_cp,  (size_t)DD*DD);

    pos_emb_kernel<<<SS, 256>>>(p_r, pb_r);
    embed_kernel<<<TT, 256>>>(decode_input, word_emb, p_core, pb_core);
    transpose_enc<<<TE, 256>>>(encoder_rep, p_enct, pb_enct);

    for (int l = 0; l < LL; l++) {
        sgemm_bf<<<dim3(3*DD/128, TT/128), 256>>>(pb_core, pw_qkv + (size_t)l*3*DD*DD, p_heads,
                                                  nullptr, nullptr, DD, DD, DD, 3*DD, 0);
        sgemm_bf<<<dim3(DD/128, SS/128), 256>>>(pb_r, pw_r + (size_t)l*DD*DD, p_rk,
                                                nullptr, nullptr, DD, DD, DD, DD, 0);
        bgemm_nt<<<dim3(1, 1, BB*HH), 256>>>(p_heads, p_heads + DD, p_AC, rw_bias + (size_t)l*HH*DHH,
            DHH, HH,
            3*DD, DHH, BB*3*DD,
            3*DD, DHH, BB*3*DD,
            (long long)HH*SS*SS, (long long)SS*SS, SS, DHH);
        bgemm_nt<<<dim3(1, 1, BB*HH), 256>>>(p_heads, p_rk, p_BD, rr_bias + (size_t)l*HH*DHH,
            DHH, HH,
            3*DD, DHH, BB*3*DD,
            0, DHH, DD,
            (long long)HH*SS*SS, (long long)SS*SS, SS, DHH);
        softmax_self<<<BB*HH*SS, 128>>>(p_AC, p_BD, p_AC);
        bgemm_nn<<<dim3(1, 1, BB*HH), 256>>>(p_AC, p_heads + 2*DD, p_vec, pb_vec,
            SS, HH,
            (long long)HH*SS*SS, (long long)SS*SS, SS,
            3*DD, DHH, BB*3*DD,
            DD, DHH, BB*DD);
        sgemm_bf<<<dim3(DD/128, TT/128), 256>>>(pb_vec, pw_o + (size_t)l*DD*DD, p_tmp,
                                                nullptr, nullptr, DD, DD, DD, DD, 0);
        add_ln<<<TT, 256>>>(p_core, p_tmp, p_x, pb_x, ln1_g + l*DD, ln1_b + l*DD);

        // cross attention
        sgemm_bf<<<dim3(2*DD/128, TE/128), 256>>>(pb_enct, pw_kv + (size_t)l*2*DD*DD, p_kv,
                                                  nullptr, nullptr, DD, DD, DD, 2*DD, 0);
        sgemm_bf<<<dim3(DD/128, TT/128), 256>>>(pb_x, pw_q + (size_t)l*DD*DD, p_q2,
                                                nullptr, nullptr, DD, DD, DD, DD, 0);
        bgemm_nt<<<dim3(EE/128, 1, BB*HH), 256>>>(p_q2, p_kv, p_s2, nullptr,
            DHH, HH,
            DD, DHH, BB*DD,
            2*DD, DHH, BB*2*DD,
            (long long)HH*SS*EE, (long long)SS*EE, EE, 0);
        softmax_cross<<<BB*HH*SS, 512>>>(p_s2, input_mask);
        bgemm_nn<<<dim3(1, 1, BB*HH), 256>>>(p_s2, p_kv + DD, p_vec, pb_vec,
            EE, HH,
            (long long)HH*SS*EE, (long long)SS*EE, EE,
            2*DD, DHH, BB*2*DD,
            DD, DHH, BB*DD);
        sgemm_bf<<<dim3(DD/128, TT/128), 256>>>(pb_vec, pw_io + (size_t)l*DD*DD, p_tmp,
                                                nullptr, nullptr, DD, DD, DD, DD, 0);
        add_ln<<<TT, 256>>>(p_x, p_tmp, p_y, pb_y, ln2_g + l*DD, ln2_b + l*DD);

        // FFN
        sgemm_bf<<<dim3(FF_/128, TT/128), 256>>>(pb_y, pw_f1 + (size_t)l*FF_*DD, nullptr,
                                                 pb_h, ffn_b1 + (size_t)l*FF_, DD, DD, DD, FF_, 1);
        sgemm_bf<<<dim3(DD/128, TT/128), 256>>>(pb_h, pw_f2 + (size_t)l*DD*FF_, p_tmp,
                                                nullptr, ffn_b2 + (size_t)l*DD, FF_, FF_, FF_, DD, 0);
        add_ln<<<TT, 256>>>(p_y, p_tmp, p_core, pb_core, ln3_g + l*DD, ln3_b + l*DD);
    }

    // output head
    sgemm_bf<<<dim3(DD/128, TT/128), 256>>>(pb_core, pw_out, nullptr, pb_outb, out_b,
                                            DD, DD, DD, DD, 0);
    sgemm_bf<<<dim3(VV/128, TT/128), 256>>>(pb_outb, pw_emb, p_log, nullptr, nullptr,
                                            DD, DD, DD, VV, 0);
    row_logit_stats<<<TT, 256>>>(p_log, p_rmax, p_rsum);

    sgemm_bf<<<dim3(DD/128, TT/128), 256>>>(pb_core, pw_cp, p_copyh, nullptr, copy_b,
                                            DD, DD, DD, DD, 0);
    bgemm_nt<<<dim3(EE/128, 1, BB), 256>>>(p_copyh, p_enct, p_IL, nullptr,
        DD, 1,
        DD, 0, BB*DD,
        DD, 0, BB*DD,
        EE, 0, BB*EE, 0);
    softmax_il<<<TT, 512>>>(p_IL, input_mask);
    mode_kernel<<<TT, 256>>>(p_core, mode_w, mode_b, p_msig);
    loss_kernel<<<1, 256>>>(p_log, p_rmax, p_rsum, p_msig, p_IL, input_ids, decode_target,
                            (float*)d_out);
}

// round 4
// speedup vs baseline: 3.7446x; 1.1669x over previous
#include <cuda_runtime.h>
#include <cuda_bf16.h>
#include <math.h>
#include <stdint.h>

// Problem dims
#define BB 8
#define SS 128
#define EE 512
#define DD 1024
#define HH 16
#define LL 4
#define VV 32000
#define DHH 64
#define FF_ 4096
#define TT (SS*BB)
#define TE (EE*BB)
#define SCALE_ 0.125f
#define NEG_ (-1e30f)

typedef __nv_bfloat16 bf16;

// ---------------- scratch ----------------
__device__ float g_r[SS*DD];
__device__ float g_core[TT*DD];
__device__ float g_x[TT*DD];
__device__ float g_y[TT*DD];
__device__ float g_tmp[TT*DD];
__device__ float g_copyh[TT*DD];
__device__ float g_enct[TE*DD];
__device__ float g_AC[BB*HH*SS*SS];
__device__ float g_BD[BB*HH*SS*SS];
__device__ float g_s2[BB*HH*SS*EE];
__device__ float g_logits[(size_t)TT*VV];
__device__ float g_IL[TT*EE];
__device__ float g_rmax[TT];
__device__ float g_rsum[TT];
__device__ float g_msig[TT];

// bf16 activations
__device__ bf16 b_core[TT*DD];
__device__ bf16 b_r[SS*DD];
__device__ bf16 b_rk[SS*DD];
__device__ bf16 b_x[TT*DD];
__device__ bf16 b_y[TT*DD];
__device__ bf16 b_vec[TT*DD];
__device__ bf16 b_enct[TE*DD];
__device__ bf16 b_h[TT*FF_];
__device__ bf16 b_outb[TT*DD];
__device__ bf16 b_heads[TT*3*DD];
__device__ bf16 b_kv[TE*2*DD];
__device__ bf16 b_q2[TT*DD];
__device__ bf16 b_P[BB*HH*SS*SS];
__device__ bf16 b_P2[BB*HH*SS*EE];

// bf16 weights
__device__ bf16 w_qkv[LL*3*DD*DD];
__device__ bf16 w_r[LL*DD*DD];
__device__ bf16 w_o[LL*DD*DD];
__device__ bf16 w_kv[LL*2*DD*DD];
__device__ bf16 w_q[LL*DD*DD];
__device__ bf16 w_io[LL*DD*DD];
__device__ bf16 w_f1[LL*FF_*DD];
__device__ bf16 w_f2[LL*DD*FF_];
__device__ bf16 w_emb[(size_t)VV*DD];
__device__ bf16 w_out[DD*DD];
__device__ bf16 w_copy[DD*DD];

__device__ __forceinline__ uint32_t smem_u32(const void* p)
{
    return (uint32_t)__cvta_generic_to_shared(p);
}

// ---------------- f32 -> bf16 conversion ----------------
__global__ void cvt_bf16(const float* __restrict__ src, bf16* __restrict__ dst, int n)
{
    int i = (blockIdx.x * 256 + threadIdx.x) * 4;
    if (i >= n) return;
    float4 v = *reinterpret_cast<const float4*>(src + i);
    uint32_t lo = ((uint32_t)__bfloat16_as_ushort(__float2bfloat16_rn(v.y)) << 16)
                | (uint32_t)__bfloat16_as_ushort(__float2bfloat16_rn(v.x));
    uint32_t hi = ((uint32_t)__bfloat16_as_ushort(__float2bfloat16_rn(v.w)) << 16)
                | (uint32_t)__bfloat16_as_ushort(__float2bfloat16_rn(v.z));
    *reinterpret_cast<uint2*>(dst + i) = make_uint2(lo, hi);
}

// ---------------- bf16 tensor-core NT GEMM (dense): C = A @ Bw^T (+bias, +gelu) -----
__global__ __launch_bounds__(256, 2)
void sgemm_bf(const bf16* __restrict__ A, const bf16* __restrict__ Bw,
              float* __restrict__ Cf, bf16* __restrict__ Cb,
              const float* __restrict__ bias,
              int K, int lda, int ldb, int ldc, int act)
{
    __shared__ bf16 As[2][128][40];
    __shared__ bf16 Bs[2][128][40];

    int tid = threadIdx.x;
    int warp = tid >> 5, lane = tid & 31;
    int warp_m = warp >> 1;
    int warp_n = warp & 1;
    int rowA0 = blockIdx.y * 128;
    int colB0 = blockIdx.x * 128;

    int ldrow = tid >> 1;
    int ldkoff = (tid & 1) * 16;

    float c[2][8][4];
#pragma unroll
    for (int mi = 0; mi < 2; mi++)
#pragma unroll
        for (int ni = 0; ni < 8; ni++)
#pragma unroll
            for (int r = 0; r < 4; r++) c[mi][ni][r] = 0.f;

    const bf16* Agp = &A[(size_t)(rowA0 + ldrow) * lda + ldkoff];
    const bf16* Bgp = &Bw[(size_t)(colB0 + ldrow) * ldb + ldkoff];

    {
        uint32_t sa = smem_u32(&As[0][ldrow][ldkoff]);
        uint32_t sb = smem_u32(&Bs[0][ldrow][ldkoff]);
        asm volatile("cp.async.ca.shared.global [%0], [%1], 16;\n"
                     "cp.async.ca.shared.global [%2], [%3], 16;\n"
                     "cp.async.ca.shared.global [%4], [%5], 16;\n"
                     "cp.async.ca.shared.global [%6], [%7], 16;\n"
                     :: "r"(sa), "l"(Agp), "r"(sa + 16), "l"(Agp + 8),
                        "r"(sb), "l"(Bgp), "r"(sb + 16), "l"(Bgp + 8));
        asm volatile("cp.async.commit_group;");
    }

    int buf = 0;
    for (int kb = 0; kb < K; kb += 32) {
        asm volatile("cp.async.wait_group 0;");
        __syncthreads();
        if (kb + 32 < K) {
            int nb = buf ^ 1;
            uint32_t sa = smem_u32(&As[nb][ldrow][ldkoff]);
            uint32_t sb = smem_u32(&Bs[nb][ldrow][ldkoff]);
            const bf16* ag = Agp + kb + 32;
            const bf16* bg = Bgp + kb + 32;
            asm volatile("cp.async.ca.shared.global [%0], [%1], 16;\n"
                         "cp.async.ca.shared.global [%2], [%3], 16;\n"
                         "cp.async.ca.shared.global [%4], [%5], 16;\n"
                         "cp.async.ca.shared.global [%6], [%7], 16;\n"
                         :: "r"(sa), "l"(ag), "r"(sa + 16), "l"(ag + 8),
                            "r"(sb), "l"(bg), "r"(sb + 16), "l"(bg + 8));
            asm volatile("cp.async.commit_group;");
        }

#pragma unroll
        for (int ks = 0; ks < 2; ks++) {
            int k0 = ks * 16;
            uint32_t a[2][4];
#pragma unroll
            for (int mi = 0; mi < 2; mi++) {
                int m = warp_m * 32 + mi * 16 + (lane & 15);
                int kc = k0 + ((lane >> 4) << 3);
                uint32_t addr = smem_u32(&As[buf][m][kc]);
                asm volatile("ldmatrix.sync.aligned.m8n8.x4.shared.b16 {%0,%1,%2,%3}, [%4];"
                             : "=r"(a[mi][0]), "=r"(a[mi][1]), "=r"(a[mi][2]), "=r"(a[mi][3])
                             : "r"(addr));
            }
            uint32_t b[8][2];
#pragma unroll
            for (int nt = 0; nt < 4; nt++) {
                int n = warp_n * 64 + nt * 16 + (lane & 7) + ((lane >> 4) << 3);
                int kc = k0 + (((lane >> 3) & 1) << 3);
                uint32_t addr = smem_u32(&Bs[buf][n][kc]);
                asm volatile("ldmatrix.sync.aligned.m8n8.x4.shared.b16 {%0,%1,%2,%3}, [%4];"
                             : "=r"(b[nt*2][0]), "=r"(b[nt*2][1]),
                               "=r"(b[nt*2+1][0]), "=r"(b[nt*2+1][1])
                             : "r"(addr));
            }
#pragma unroll
            for (int mi = 0; mi < 2; mi++)
#pragma unroll
                for (int ni = 0; ni < 8; ni++) {
                    asm volatile(
                        "mma.sync.aligned.m16n8k16.row.col.f32.bf16.bf16.f32 "
                        "{%0,%1,%2,%3}, {%4,%5,%6,%7}, {%8,%9}, {%0,%1,%2,%3};\n"
                        : "+f"(c[mi][ni][0]), "+f"(c[mi][ni][1]),
                          "+f"(c[mi][ni][2]), "+f"(c[mi][ni][3])
                        : "r"(a[mi][0]), "r"(a[mi][1]), "r"(a[mi][2]), "r"(a[mi][3]),
                          "r"(b[ni][0]), "r"(b[ni][1]));
                }
        }
        buf ^= 1;
        __syncthreads();
    }

#pragma unroll
    for (int mi = 0; mi < 2; mi++) {
        int row0 = rowA0 + warp_m * 32 + mi * 16 + (lane >> 2);
#pragma unroll
        for (int ni = 0; ni < 8; ni++) {
            int col = colB0 + warp_n * 64 + ni * 8 + (lane & 3) * 2;
            float bv0 = 0.f, bv1 = 0.f;
            if (bias) { bv0 = bias[col]; bv1 = bias[col + 1]; }
#pragma unroll
            for (int half = 0; half < 2; half++) {
                int gm = row0 + half * 8;
                float v0 = c[mi][ni][half * 2 + 0] + bv0;
                float v1 = c[mi][ni][half * 2 + 1] + bv1;
                if (act == 1) {
                    v0 = 0.5f * v0 * (1.0f + erff(v0 * 0.70710678118654752f));
                    v1 = 0.5f * v1 * (1.0f + erff(v1 * 0.70710678118654752f));
                }
                if (Cf) {
                    Cf[(size_t)gm * ldc + col]     = v0;
                    Cf[(size_t)gm * ldc + col + 1] = v1;
                }
                if (Cb) {
                    uint32_t pk = ((uint32_t)__bfloat16_as_ushort(__float2bfloat16_rn(v1)) << 16)
                                | (uint32_t)__bfloat16_as_ushort(__float2bfloat16_rn(v0));
                    *reinterpret_cast<uint32_t*>(&Cb[(size_t)gm * ldc + col]) = pk;
                }
            }
        }
    }
}

// ---------------- batched bf16 NT mma (M=128, K=64): scores -------------------------
// C[i,n] = sum_k (A[i,k]+abias[k]) * B[n,k], fp32 out.
__global__ __launch_bounds__(256, 2)
void bmm_nt_bf(const bf16* __restrict__ A, const bf16* __restrict__ B,
               float* __restrict__ C, const float* __restrict__ abias,
               int Hdim,
               long long aSB, long long aSH, int aRow,
               long long bSB, long long bSH, int bRow,
               long long cSB, long long cSH, int cRow, int abiasH)
{
    __shared__ bf16 As[128][72];
    __shared__ bf16 Bs[128][72];
    int z = blockIdx.z;
    int h = z % Hdim, b = z / Hdim;
    const bf16* Ab = A + (size_t)b * aSB + (size_t)h * aSH;
    const bf16* Bb = B + (size_t)b * bSB + (size_t)h * bSH + (size_t)blockIdx.x * 128 * bRow;
    float* Cb = C + (size_t)b * cSB + (size_t)h * cSH + blockIdx.x * 128;
    const float* biasb = abias ? (abias + (size_t)h * abiasH) : nullptr;

    int tid = threadIdx.x;
    int warp = tid >> 5, lane = tid & 31;
    int warp_m = warp >> 1, warp_n = warp & 1;
    int row = tid >> 1, koff = (tid & 1) * 32;

    {
        const bf16* ap = Ab + (size_t)row * aRow + koff;
#pragma unroll
        for (int j = 0; j < 4; j++) {
            uint4 v = *reinterpret_cast<const uint4*>(ap + j * 8);
            if (biasb) {
                bf16 tmp[8];
                *reinterpret_cast<uint4*>(tmp) = v;
#pragma unroll
                for (int e = 0; e < 8; e++)
                    tmp[e] = __float2bfloat16_rn(__bfloat162float(tmp[e]) + biasb[koff + j*8 + e]);
                v = *reinterpret_cast<uint4*>(tmp);
            }
            *reinterpret_cast<uint4*>(&As[row][koff + j*8]) = v;
        }
        const bf16* bp = Bb + (size_t)row * bRow + koff;
#pragma unroll
        for (int j = 0; j < 4; j++)
            *reinterpret_cast<uint4*>(&Bs[row][koff + j*8]) = *reinterpret_cast<const uint4*>(bp + j*8);
    }
    __syncthreads();

    float c[2][8][4];
#pragma unroll
    for (int mi = 0; mi < 2; mi++)
#pragma unroll
        for (int ni = 0; ni < 8; ni++)
#pragma unroll
            for (int r = 0; r < 4; r++) c[mi][ni][r] = 0.f;

#pragma unroll
    for (int ks = 0; ks < 4; ks++) {
        int k0 = ks * 16;
        uint32_t a[2][4];
#pragma unroll
        for (int mi = 0; mi < 2; mi++) {
            int m = warp_m * 32 + mi * 16 + (lane & 15);
            int kc = k0 + ((lane >> 4) << 3);
            uint32_t addr = smem_u32(&As[m][kc]);
            asm volatile("ldmatrix.sync.aligned.m8n8.x4.shared.b16 {%0,%1,%2,%3}, [%4];"
                         : "=r"(a[mi][0]), "=r"(a[mi][1]), "=r"(a[mi][2]), "=r"(a[mi][3])
                         : "r"(addr));
        }
        uint32_t bb[8][2];
#pragma unroll
        for (int nt = 0; nt < 4; nt++) {
            int n = warp_n * 64 + nt * 16 + (lane & 7) + ((lane >> 4) << 3);
            int kc = k0 + (((lane >> 3) & 1) << 3);
            uint32_t addr = smem_u32(&Bs[n][kc]);
            asm volatile("ldmatrix.sync.aligned.m8n8.x4.shared.b16 {%0,%1,%2,%3}, [%4];"
                         : "=r"(bb[nt*2][0]), "=r"(bb[nt*2][1]),
                           "=r"(bb[nt*2+1][0]), "=r"(bb[nt*2+1][1])
                         : "r"(addr));
        }
#pragma unroll
        for (int mi = 0; mi < 2; mi++)
#pragma unroll
            for (int ni = 0; ni < 8; ni++) {
                asm volatile(
                    "mma.sync.aligned.m16n8k16.row.col.f32.bf16.bf16.f32 "
                    "{%0,%1,%2,%3}, {%4,%5,%6,%7}, {%8,%9}, {%0,%1,%2,%3};\n"
                    : "+f"(c[mi][ni][0]), "+f"(c[mi][ni][1]),
                      "+f"(c[mi][ni][2]), "+f"(c[mi][ni][3])
                    : "r"(a[mi][0]), "r"(a[mi][1]), "r"(a[mi][2]), "r"(a[mi][3]),
                      "r"(bb[ni][0]), "r"(bb[ni][1]));
            }
    }

#pragma unroll
    for (int mi = 0; mi < 2; mi++) {
        int row0 = warp_m * 32 + mi * 16 + (lane >> 2);
#pragma unroll
        for (int ni = 0; ni < 8; ni++) {
            int col = warp_n * 64 + ni * 8 + (lane & 3) * 2;
#pragma unroll
            for (int half = 0; half < 2; half++) {
                int gm = row0 + half * 8;
                Cb[(size_t)gm * cRow + col]     = c[mi][ni][half*2 + 0];
                Cb[(size_t)gm * cRow + col + 1] = c[mi][ni][half*2 + 1];
            }
        }
    }
}

// ---------------- batched bf16 NN mma (M=128, N=64): C = P @ V ----------------------
// P [128,K] bf16 row-major, V [K,64] bf16 rows (ldmatrix.trans). bf16 out.
__global__ __launch_bounds__(256, 2)
void bmm_nn_bf(const bf16* __restrict__ A, const bf16* __restrict__ B,
               bf16* __restrict__ Cb2,
               int K, int Hdim,
               long long aSB, long long aSH, int aRow,
               long long bSB, long long bSH, int bRow,
               long long cSB, long long cSH, int cRow)
{
    __shared__ bf16 As[128][72];
    __shared__ bf16 Bs[64][72];
    int z = blockIdx.z;
    int h = z % Hdim, b = z / Hdim;
    const bf16* Ab = A + (size_t)b * aSB + (size_t)h * aSH;
    const bf16* Bb = B + (size_t)b * bSB + (size_t)h * bSH;
    bf16* Cb = Cb2 + (size_t)b * cSB + (size_t)h * cSH;

    int tid = threadIdx.x;
    int warp = tid >> 5, lane = tid & 31;
    int warp_m = warp >> 1, warp_n = warp & 1;   // warp tile 32(M) x 32(N)
    int rowA = tid >> 1, koffA = (tid & 1) * 32;
    int rowB = tid >> 2, doffB = (tid & 3) * 16;

    float c[2][4][4];
#pragma unroll
    for (int mi = 0; mi < 2; mi++)
#pragma unroll
        for (int ni = 0; ni < 4; ni++)
#pragma unroll
            for (int r = 0; r < 4; r++) c[mi][ni][r] = 0.f;

    for (int kb = 0; kb < K; kb += 64) {
        const bf16* ap = Ab + (size_t)rowA * aRow + kb + koffA;
#pragma unroll
        for (int j = 0; j < 4; j++)
            *reinterpret_cast<uint4*>(&As[rowA][koffA + j*8]) =
                *reinterpret_cast<const uint4*>(ap + j*8);
        const bf16* bp = Bb + (size_t)(kb + rowB) * bRow + doffB;
#pragma unroll
        for (int j = 0; j < 2; j++)
            *reinterpret_cast<uint4*>(&Bs[rowB][doffB + j*8]) =
                *reinterpret_cast<const uint4*>(bp + j*8);
        __syncthreads();

#pragma unroll
        for (int ks = 0; ks < 4; ks++) {
            int k0 = ks * 16;
            uint32_t a[2][4];
#pragma unroll
            for (int mi = 0; mi < 2; mi++) {
                int m = warp_m * 32 + mi * 16 + (lane & 15);
                int kc = k0 + ((lane >> 4) << 3);
                uint32_t addr = smem_u32(&As[m][kc]);
                asm volatile("ldmatrix.sync.aligned.m8n8.x4.shared.b16 {%0,%1,%2,%3}, [%4];"
                             : "=r"(a[mi][0]), "=r"(a[mi][1]), "=r"(a[mi][2]), "=r"(a[mi][3])
                             : "r"(addr));
            }
            uint32_t bb[4][2];
#pragma unroll
            for (int nt = 0; nt < 2; nt++) {
                int kr = k0 + (lane & 15);
                int n = warp_n * 32 + nt * 16 + ((lane >> 4) << 3);
                uint32_t addr = smem_u32(&Bs[kr][n]);
                asm volatile("ldmatrix.sync.aligned.m8n8.x4.trans.shared.b16 {%0,%1,%2,%3}, [%4];"
                             : "=r"(bb[nt*2][0]), "=r"(bb[nt*2][1]),
                               "=r"(bb[nt*2+1][0]), "=r"(bb[nt*2+1][1])
                             : "r"(addr));
            }
#pragma unroll
            for (int mi = 0; mi < 2; mi++)
#pragma unroll
                for (int ni = 0; ni < 4; ni++) {
                    asm volatile(
                        "mma.sync.aligned.m16n8k16.row.col.f32.bf16.bf16.f32 "
                        "{%0,%1,%2,%3}, {%4,%5,%6,%7}, {%8,%9}, {%0,%1,%2,%3};\n"
                        : "+f"(c[mi][ni][0]), "+f"(c[mi][ni][1]),
                          "+f"(c[mi][ni][2]), "+f"(c[mi][ni][3])
                        : "r"(a[mi][0]), "r"(a[mi][1]), "r"(a[mi][2]), "r"(a[mi][3]),
                          "r"(bb[ni][0]), "r"(bb[ni][1]));
                }
        }
        __syncthreads();
    }

#pragma unroll
    for (int mi = 0; mi < 2; mi++) {
        int row0 = warp_m * 32 + mi * 16 + (lane >> 2);
#pragma unroll
        for (int ni = 0; ni < 4; ni++) {
            int col = warp_n * 32 + ni * 8 + (lane & 3) * 2;
#pragma unroll
            for (int half = 0; half < 2; half++) {
                int gm = row0 + half * 8;
                uint32_t pk = ((uint32_t)__bfloat16_as_ushort(__float2bfloat16_rn(c[mi][ni][half*2+1])) << 16)
                            | (uint32_t)__bfloat16_as_ushort(__float2bfloat16_rn(c[mi][ni][half*2+0]));
                *reinterpret_cast<uint32_t*>(&Cb[(size_t)gm * cRow + col]) = pk;
            }
        }
    }
}

// ---------------- batched fp32 NT gemm (copy-attn IL only) ---------------------------
__global__ __launch_bounds__(256, 2)
void bgemm_nt(const float* __restrict__ A, const float* __restrict__ Bp,
              float* __restrict__ C,
              int K,
              long long aSB, int aRow,
              long long bSB, int bRow,
              long long cSB, int cRow)
{
    __shared__ float As[16][132];
    __shared__ float Bs[16][132];
    int b = blockIdx.z;
    const float* Ab = A + (size_t)b * aSB;
    const float* Bb = Bp + (size_t)b * bSB;
    float* Cb = C + (size_t)b * cSB;

    int tid = threadIdx.x;
    int tx = tid & 15, ty = tid >> 4;
    int m0 = ty * 8, n0 = tx * 8;
    int colB0 = blockIdx.x * 128;
    int r  = tid >> 2;
    int c4 = (tid & 3) * 4;
    float acc[8][8];
#pragma unroll
    for (int i = 0; i < 8; i++)
#pragma unroll
        for (int j = 0; j < 8; j++) acc[i][j] = 0.f;

    for (int kb = 0; kb < K; kb += 16) {
#pragma unroll
        for (int half = 0; half < 2; half++) {
            int rr = r + half * 64;
            float4 av = *reinterpret_cast<const float4*>(&Ab[(size_t)rr * aRow + kb + c4]);
            As[c4+0][rr] = av.x; As[c4+1][rr] = av.y; As[c4+2][rr] = av.z; As[c4+3][rr] = av.w;
            float4 bv = *reinterpret_cast<const float4*>(&Bb[(size_t)(colB0 + rr) * bRow + kb + c4]);
            Bs[c4+0][rr] = bv.x; Bs[c4+1][rr] = bv.y; Bs[c4+2][rr] = bv.z; Bs[c4+3][rr] = bv.w;
        }
        __syncthreads();
#pragma unroll
        for (int kk = 0; kk < 16; kk++) {
            float a[8], bb[8];
            *reinterpret_cast<float4*>(a)      = *reinterpret_cast<const float4*>(&As[kk][m0]);
            *reinterpret_cast<float4*>(a + 4)  = *reinterpret_cast<const float4*>(&As[kk][m0 + 4]);
            *reinterpret_cast<float4*>(bb)     = *reinterpret_cast<const float4*>(&Bs[kk][n0]);
            *reinterpret_cast<float4*>(bb + 4) = *reinterpret_cast<const float4*>(&Bs[kk][n0 + 4]);
#pragma unroll
            for (int i = 0; i < 8; i++)
#pragma unroll
                for (int j = 0; j < 8; j++) acc[i][j] += a[i] * bb[j];
        }
        __syncthreads();
    }
#pragma unroll
    for (int i = 0; i < 8; i++)
#pragma unroll
        for (int j = 0; j < 8; j++)
            Cb[(size_t)(m0 + i) * cRow + colB0 + n0 + j] = acc[i][j];
}

// ---------------- misc small kernels --------------------------------------------------
__global__ void pos_emb_kernel(float* __restrict__ r, bf16* __restrict__ rb)
{
    int i = blockIdx.x;
    float pos = (float)(SS - 1 - i);
    const float LOG1E4 = 9.210340371976184f;
    for (int d = threadIdx.x; d < DD; d += 256) {
        int j = (d < DD/2) ? d : d - DD/2;
        float invf = expf(-((float)j / (DD/2)) * LOG1E4);
        float a = pos * invf;
        float v = (d < DD/2) ? sinf(a) : cosf(a);
        r[i * DD + d] = v;
        rb[i * DD + d] = __float2bfloat16_rn(v);
    }
}

__global__ void embed_kernel(const int* __restrict__ dec, const float* __restrict__ emb,
                             float* __restrict__ core, bf16* __restrict__ coreb)
{
    int t = blockIdx.x;
    int b = t & (BB-1), s = t >> 3;
    int id = dec[b * SS + s];
    const float* src = emb + (size_t)id * DD;
    for (int d = threadIdx.x; d < DD; d += 256) {
        float v = src[d];
        core[(size_t)t * DD + d] = v;
        coreb[(size_t)t * DD + d] = __float2bfloat16_rn(v);
    }
}

__global__ void transpose_enc(const float* __restrict__ enc, float* __restrict__ enct,
                              bf16* __restrict__ enctb)
{
    int t = blockIdx.x;
    int b = t & (BB-1), e = t >> 3;
    const float* src = enc + ((size_t)b * EE + e) * DD;
    for (int d = threadIdx.x; d < DD; d += 256) {
        float v = src[d];
        enct[(size_t)t * DD + d] = v;
        enctb[(size_t)t * DD + d] = __float2bfloat16_rn(v);
    }
}

// self-attn: score=(AC+relshift(BD))*SCALE, causal, softmax over j; bf16 out.
__global__ void softmax_self(const float* __restrict__ AC, const float* __restrict__ BD,
                             bf16* __restrict__ P)
{
    int row = blockIdx.x;
    int i = row & (SS - 1);
    int bhBase = row - i;
    int j = threadIdx.x;
    float acv = AC[(size_t)row * SS + j];
    int f = i * SS + j + SS;
    int qi = f / (SS + 1), c = f % (SS + 1);
    float bd = (c > 0) ? BD[(size_t)(bhBase + qi) * SS + (c - 1)] : 0.0f;
    float s = (acv + bd) * SCALE_;
    if (j > i) s = NEG_;
    __shared__ float sh[128];
    sh[j] = s; __syncthreads();
    for (int st = 64; st > 0; st >>= 1) { if (j < st) sh[j] = fmaxf(sh[j], sh[j + st]); __syncthreads(); }
    float mx = sh[0]; __syncthreads();
    float e = expf(s - mx);
    sh[j] = e; __syncthreads();
    for (int st = 64; st > 0; st >>= 1) { if (j < st) sh[j] += sh[j + st]; __syncthreads(); }
    P[(size_t)row * SS + j] = __float2bfloat16_rn(e / sh[0]);
}

__global__ void softmax_cross(const float* __restrict__ S2, const float* __restrict__ mask,
                              bf16* __restrict__ P)
{
    int row = blockIdx.x;
    int b = row / (HH * SS);
    int k = threadIdx.x;
    float v = S2[(size_t)row * EE + k] * SCALE_ + (1.0f - mask[b * EE + k]) * NEG_;
    __shared__ float sh[512];
    sh[k] = v; __syncthreads();
    for (int st = 256; st > 0; st >>= 1) { if (k < st) sh[k] = fmaxf(sh[k], sh[k + st]); __syncthreads(); }
    float mx = sh[0]; __syncthreads();
    float e = expf(v - mx);
    sh[k] = e; __syncthreads();
    for (int st = 256; st > 0; st >>= 1) { if (k < st) sh[k] += sh[k + st]; __syncthreads(); }
    P[(size_t)row * EE + k] = __float2bfloat16_rn(e / sh[0]);
}

__global__ void softmax_il(float* __restrict__ IL, const float* __restrict__ mask)
{
    int t = blockIdx.x;
    int b = t & (BB - 1);
    int k = threadIdx.x;
    float v = IL[(size_t)t * EE + k] + (1.0f - mask[b * EE + k]) * NEG_;
    __shared__ float sh[512];
    sh[k] = v; __syncthreads();
    for (int st = 256; st > 0; st >>= 1) { if (k < st) sh[k] = fmaxf(sh[k], sh[k + st]); __syncthreads(); }
    float mx = sh[0]; __syncthreads();
    float e = expf(v - mx);
    sh[k] = e; __syncthreads();
    for (int st = 256; st > 0; st >>= 1) { if (k < st) sh[k] += sh[k + st]; __syncthreads(); }
    IL[(size_t)t * EE + k] = e / sh[0];
}

__global__ void add_ln(const float* __restrict__ resid, const float* __restrict__ add,
                       float* __restrict__ out, bf16* __restrict__ outb,
                       const float* __restrict__ g, const float* __restrict__ bta)
{
    int t = blockIdx.x;
    int tid = threadIdx.x;
    __shared__ float zb[DD];
    __shared__ float red[256];
    float s = 0.f;
#pragma unroll
    for (int u = 0; u < 4; u++) {
        int d = tid + u * 256;
        float z = resid[(size_t)t * DD + d] + add[(size_t)t * DD + d];
        zb[d] = z; s += z;
    }
    red[tid] = s; __syncthreads();
    for (int st = 128; st > 0; st >>= 1) { if (tid < st) red[tid] += red[tid + st]; __syncthreads(); }
    float mean = red[0] * (1.0f / DD); __syncthreads();
    float v = 0.f;
#pragma unroll
    for (int u = 0; u < 4; u++) {
        int d = tid + u * 256;
        float dz = zb[d] - mean; v += dz * dz;
    }
    red[tid] = v; __syncthreads();
    for (int st = 128; st > 0; st >>= 1) { if (tid < st) red[tid] += red[tid + st]; __syncthreads(); }
    float inv = rsqrtf(red[0] * (1.0f / DD) + 1e-5f);
#pragma unroll
    for (int u = 0; u < 4; u++) {
        int d = tid + u * 256;
        float o = (zb[d] - mean) * inv * g[d] + bta[d];
        out[(size_t)t * DD + d] = o;
        if (outb) outb[(size_t)t * DD + d] = __float2bfloat16_rn(o);
    }
}

__global__ void row_logit_stats(const float* __restrict__ Lg, float* __restrict__ rmax,
                                float* __restrict__ rsum)
{
    int t = blockIdx.x;
    int tid = threadIdx.x;
    const float* row = Lg + (size_t)t * VV;
    float m = -1e30f;
    for (int v = tid * 4; v < VV; v += 1024) {
        float4 x = *reinterpret_cast<const float4*>(row + v);
        m = fmaxf(m, fmaxf(fmaxf(x.x, x.y), fmaxf(x.z, x.w)));
    }
    __shared__ float red[256];
    red[tid] = m; __syncthreads();
    for (int st = 128; st > 0; st >>= 1) { if (tid < st) red[tid] = fmaxf(red[tid], red[tid + st]); __syncthreads(); }
    m = red[0]; __syncthreads();
    float s = 0.f;
    for (int v = tid * 4; v < VV; v += 1024) {
        float4 x = *reinterpret_cast<const float4*>(row + v);
        s += expf(x.x - m) + expf(x.y - m) + expf(x.z - m) + expf(x.w - m);
    }
    red[tid] = s; __syncthreads();
    for (int st = 128; st > 0; st >>= 1) { if (tid < st) red[tid] += red[tid + st]; __syncthreads(); }
    if (tid == 0) { rmax[t] = m; rsum[t] = red[0]; }
}

__global__ void mode_kernel(const float* __restrict__ core, const float* __restrict__ mw,
                            const float* __restrict__ mb, float* __restrict__ msig)
{
    int t = blockIdx.x;
    int tid = threadIdx.x;
    float s = 0.f;
    for (int d = tid; d < DD; d += 256) s += core[(size_t)t * DD + d] * mw[d];
    __shared__ float red[256];
    red[tid] = s; __syncthreads();
    for (int st = 128; st > 0; st >>= 1) { if (tid < st) red[tid] += red[tid + st]; __syncthreads(); }
    if (tid == 0) msig[t] = 1.0f / (1.0f + expf(-(red[0] + mb[0])));
}

__global__ void loss_kernel(const float* __restrict__ logits, const float* __restrict__ rmax,
                            const float* __restrict__ rsum, const float* __restrict__ msig,
                            const float* __restrict__ IL, const int* __restrict__ input_ids,
                            const int* __restrict__ decode_target, float* __restrict__ out)
{
    int tid = threadIdx.x;
    float acc = 0.f, cnt = 0.f;
    for (int t = tid; t < TT; t += 256) {
        int b = t & (BB - 1), s = t >> 3;
        int tgt = decode_target[b * SS + s];
        if (tgt == 0) continue;
        float m = msig[t];
        float p = expf(logits[(size_t)t * VV + tgt] - rmax[t]) / rsum[t] * m;
        const int* ids = input_ids + b * EE;
        const float* il = IL + (size_t)t * EE;
        float cp = 0.f;
        for (int j = 0; j < EE; j++) if (ids[j] == tgt) cp += il[j];
        p += (1.0f - m) * cp;
        acc += -logf(p + 1e-6f);
        cnt += 1.0f;
    }
    __shared__ float sa[256], sc[256];
    sa[tid] = acc; sc[tid] = cnt; __syncthreads();
    for (int st = 128; st > 0; st >>= 1) {
        if (tid < st) { sa[tid] += sa[tid + st]; sc[tid] += sc[tid + st]; }
        __syncthreads();
    }
    if (tid < BB) out[tid] = sa[0] / sc[0];
}

// ---------------- host orchestration --------------------------------------------------
static void* symaddr(const void* sym)
{
    void* p = nullptr;
    cudaGetSymbolAddress(&p, sym);
    return p;
}

static void cvt(const float* src, bf16* dst, size_t n)
{
    int blocks = (int)((n / 4 + 255) / 256);
    cvt_bf16<<<blocks, 256>>>(src, dst, (int)n);
}

extern "C" void kernel_launch(void* const* d_in, const int* in_sizes, int n_in,
                              void* d_out, int out_size)
{
    const int*   input_ids     = (const int*)d_in[0];
    const float* encoder_rep   = (const float*)d_in[1];
    const float* input_mask    = (const float*)d_in[2];
    const int*   decode_input  = (const int*)d_in[3];
    const int*   decode_target = (const int*)d_in[4];
    const float* word_emb      = (const float*)d_in[5];
    const float* qkv_w         = (const float*)d_in[6];
    const float* r_w           = (const float*)d_in[7];
    const float* o_w           = (const float*)d_in[8];
    const float* kv_w          = (const float*)d_in[9];
    const float* q_w           = (const float*)d_in[10];
    const float* io_w          = (const float*)d_in[11];
    const float* rr_bias       = (const float*)d_in[12];
    const float* rw_bias       = (const float*)d_in[13];
    const float* ln1_g         = (const float*)d_in[14];
    const float* ln1_b         = (const float*)d_in[15];
    const float* ln2_g         = (const float*)d_in[16];
    const float* ln2_b         = (const float*)d_in[17];
    const float* ffn_w1        = (const float*)d_in[18];
    const float* ffn_b1        = (const float*)d_in[19];
    const float* ffn_w2        = (const float*)d_in[20];
    const float* ffn_b2        = (const float*)d_in[21];
    const float* ln3_g         = (const float*)d_in[22];
    const float* ln3_b         = (const float*)d_in[23];
    const float* out_w         = (const float*)d_in[24];
    const float* out_b         = (const float*)d_in[25];
    const float* copy_w        = (const float*)d_in[26];
    const float* copy_b        = (const float*)d_in[27];
    const float* mode_w        = (const float*)d_in[28];
    const float* mode_b        = (const float*)d_in[29];

    float* p_r     = (float*)symaddr(g_r);
    float* p_core  = (float*)symaddr(g_core);
    float* p_x     = (float*)symaddr(g_x);
    float* p_y     = (float*)symaddr(g_y);
    float* p_tmp   = (float*)symaddr(g_tmp);
    float* p_copyh = (float*)symaddr(g_copyh);
    float* p_enct  = (float*)symaddr(g_enct);
    float* p_AC    = (float*)symaddr(g_AC);
    float* p_BD    = (float*)symaddr(g_BD);
    float* p_s2    = (float*)symaddr(g_s2);
    float* p_log   = (float*)symaddr(g_logits);
    float* p_IL    = (float*)symaddr(g_IL);
    float* p_rmax  = (float*)symaddr(g_rmax);
    float* p_rsum  = (float*)symaddr(g_rsum);
    float* p_msig  = (float*)symaddr(g_msig);

    bf16* pb_core = (bf16*)symaddr(b_core);
    bf16* pb_r    = (bf16*)symaddr(b_r);
    bf16* pb_rk   = (bf16*)symaddr(b_rk);
    bf16* pb_x    = (bf16*)symaddr(b_x);
    bf16* pb_y    = (bf16*)symaddr(b_y);
    bf16* pb_vec  = (bf16*)symaddr(b_vec);
    bf16* pb_enct = (bf16*)symaddr(b_enct);
    bf16* pb_h    = (bf16*)symaddr(b_h);
    bf16* pb_outb = (bf16*)symaddr(b_outb);
    bf16* pb_heads= (bf16*)symaddr(b_heads);
    bf16* pb_kv   = (bf16*)symaddr(b_kv);
    bf16* pb_q2   = (bf16*)symaddr(b_q2);
    bf16* pb_P    = (bf16*)symaddr(b_P);
    bf16* pb_P2   = (bf16*)symaddr(b_P2);

    bf16* pw_qkv = (bf16*)symaddr(w_qkv);
    bf16* pw_r   = (bf16*)symaddr(w_r);
    bf16* pw_o   = (bf16*)symaddr(w_o);
    bf16* pw_kv  = (bf16*)symaddr(w_kv);
    bf16* pw_q   = (bf16*)symaddr(w_q);
    bf16* pw_io  = (bf16*)symaddr(w_io);
    bf16* pw_f1  = (bf16*)symaddr(w_f1);
    bf16* pw_f2  = (bf16*)symaddr(w_f2);
    bf16* pw_emb = (bf16*)symaddr(w_emb);
    bf16* pw_out = (bf16*)symaddr(w_out);
    bf16* pw_cp  = (bf16*)symaddr(w_copy);

    cvt(qkv_w,  pw_qkv, (size_t)LL*3*DD*DD);
    cvt(r_w,    pw_r,   (size_t)LL*DD*DD);
    cvt(o_w,    pw_o,   (size_t)LL*DD*DD);
    cvt(kv_w,   pw_kv,  (size_t)LL*2*DD*DD);
    cvt(q_w,    pw_q,   (size_t)LL*DD*DD);
    cvt(io_w,   pw_io,  (size_t)LL*DD*DD);
    cvt(ffn_w1, pw_f1,  (size_t)LL*FF_*DD);
    cvt(ffn_w2, pw_f2,  (size_t)LL*DD*FF_);
    cvt(word_emb, pw_emb, (size_t)VV*DD);
    cvt(out_w,  pw_out, (size_t)DD*DD);
    cvt(copy_w, pw_cp,  (size_t)DD*DD);

    pos_emb_kernel<<<SS, 256>>>(p_r, pb_r);
    embed_kernel<<<TT, 256>>>(decode_input, word_emb, p_core, pb_core);
    transpose_enc<<<TE, 256>>>(encoder_rep, p_enct, pb_enct);

    for (int l = 0; l < LL; l++) {
        sgemm_bf<<<dim3(3*DD/128, TT/128), 256>>>(pb_core, pw_qkv + (size_t)l*3*DD*DD, nullptr,
                                                  pb_heads, nullptr, DD, DD, DD, 3*DD, 0);
        sgemm_bf<<<dim3(DD/128, SS/128), 256>>>(pb_r, pw_r + (size_t)l*DD*DD, nullptr,
                                                pb_rk, nullptr, DD, DD, DD, DD, 0);
        // AC = (q + rw_bias) . k
        bmm_nt_bf<<<dim3(1, 1, BB*HH), 256>>>(pb_heads, pb_heads + DD, p_AC,
            rw_bias + (size_t)l*HH*DHH, HH,
            3*DD, DHH, BB*3*DD,
            3*DD, DHH, BB*3*DD,
            (long long)HH*SS*SS, (long long)SS*SS, SS, DHH);
        // BD = (q + rr_bias) . r_k
        bmm_nt_bf<<<dim3(1, 1, BB*HH), 256>>>(pb_heads, pb_rk, p_BD,
            rr_bias + (size_t)l*HH*DHH, HH,
            3*DD, DHH, BB*3*DD,
            0, DHH, DD,
            (long long)HH*SS*SS, (long long)SS*SS, SS, DHH);
        softmax_self<<<BB*HH*SS, 128>>>(p_AC, p_BD, pb_P);
        // vec = P @ v
        bmm_nn_bf<<<dim3(1, 1, BB*HH), 256>>>(pb_P, pb_heads + 2*DD, pb_vec,
            SS, HH,
            (long long)HH*SS*SS, (long long)SS*SS, SS,
            3*DD, DHH, BB*3*DD,
            DD, DHH, BB*DD);
        sgemm_bf<<<dim3(DD/128, TT/128), 256>>>(pb_vec, pw_o + (size_t)l*DD*DD, p_tmp,
                                                nullptr, nullptr, DD, DD, DD, DD, 0);
        add_ln<<<TT, 256>>>(p_core, p_tmp, p_x, pb_x, ln1_g + l*DD, ln1_b + l*DD);

        // cross attention
        sgemm_bf<<<dim3(2*DD/128, TE/128), 256>>>(pb_enct, pw_kv + (size_t)l*2*DD*DD, nullptr,
                                                  pb_kv, nullptr, DD, DD, DD, 2*DD, 0);
        sgemm_bf<<<dim3(DD/128, TT/128), 256>>>(pb_x, pw_q + (size_t)l*DD*DD, nullptr,
                                                pb_q2, nullptr, DD, DD, DD, DD, 0);
        bmm_nt_bf<<<dim3(EE/128, 1, BB*HH), 256>>>(pb_q2, pb_kv, p_s2, nullptr, HH,
            DD, DHH, BB*DD,
            2*DD, DHH, BB*2*DD,
            (long long)HH*SS*EE, (long long)SS*EE, EE, 0);
        softmax_cross<<<BB*HH*SS, 512>>>(p_s2, input_mask, pb_P2);
        bmm_nn_bf<<<dim3(1, 1, BB*HH), 256>>>(pb_P2, pb_kv + DD, pb_vec,
            EE, HH,
            (long long)HH*SS*EE, (long long)SS*EE, EE,
            2*DD, DHH, BB*2*DD,
            DD, DHH, BB*DD);
        sgemm_bf<<<dim3(DD/128, TT/128), 256>>>(pb_vec, pw_io + (size_t)l*DD*DD, p_tmp,
                                                nullptr, nullptr, DD, DD, DD, DD, 0);
        add_ln<<<TT, 256>>>(p_x, p_tmp, p_y, pb_y, ln2_g + l*DD, ln2_b + l*DD);

        // FFN
        sgemm_bf<<<dim3(FF_/128, TT/128), 256>>>(pb_y, pw_f1 + (size_t)l*FF_*DD, nullptr,
                                                 pb_h, ffn_b1 + (size_t)l*FF_, DD, DD, DD, FF_, 1);
        sgemm_bf<<<dim3(DD/128, TT/128), 256>>>(pb_h, pw_f2 + (size_t)l*DD*FF_, p_tmp,
                                                nullptr, ffn_b2 + (size_t)l*DD, FF_, FF_, FF_, DD, 0);
        add_ln<<<TT, 256>>>(p_y, p_tmp, p_core, pb_core, ln3_g + l*DD, ln3_b + l*DD);
    }

    // output head
    sgemm_bf<<<dim3(DD/128, TT/128), 256>>>(pb_core, pw_out, nullptr, pb_outb, out_b,
                                            DD, DD, DD, DD, 0);
    sgemm_bf<<<dim3(VV/128, TT/128), 256>>>(pb_outb, pw_emb, p_log, nullptr, nullptr,
                                            DD, DD, DD, VV, 0);
    row_logit_stats<<<TT, 256>>>(p_log, p_rmax, p_rsum);

    sgemm_bf<<<dim3(DD/128, TT/128), 256>>>(pb_core, pw_cp, p_copyh, nullptr, copy_b,
                                            DD, DD, DD, DD, 0);
    bgemm_nt<<<dim3(EE/128, 1, BB), 256>>>(p_copyh, p_enct, p_IL,
        DD,
        DD, BB*DD,
        DD, BB*DD,
        EE, BB*EE);
    softmax_il<<<TT, 512>>>(p_IL, input_mask);
    mode_kernel<<<TT, 256>>>(p_core, mode_w, mode_b, p_msig);
    loss_kernel<<<1, 256>>>(p_log, p_rmax, p_rsum, p_msig, p_IL, input_ids, decode_target,
                            (float*)d_out);
}

// round 5
// speedup vs baseline: 4.8818x; 1.3037x over previous
#include <cuda_runtime.h>
#include <cuda_bf16.h>
#include <math.h>
#include <stdint.h>

// Problem dims
#define BB 8
#define SS 128
#define EE 512
#define DD 1024
#define HH 16
#define LL 4
#define VV 32000
#define DHH 64
#define FF_ 4096
#define TT (SS*BB)
#define TE (EE*BB)
#define SCALE_ 0.125f
#define NEG_ (-1e30f)

typedef __nv_bfloat16 bf16;

// ---------------- scratch ----------------
__device__ float g_r[SS*DD];
__device__ float g_core[TT*DD];
__device__ float g_x[TT*DD];
__device__ float g_y[TT*DD];
__device__ float g_tmp[TT*DD];
__device__ float g_copyh[TT*DD];
__device__ float g_enct[TE*DD];
__device__ float g_AC[BB*HH*SS*SS];
__device__ float g_BD[BB*HH*SS*SS];
__device__ float g_s2[BB*HH*SS*EE];
__device__ float g_logits[(size_t)TT*VV];
__device__ float g_IL[TT*EE];
__device__ float g_rmax[TT];
__device__ float g_rsum[TT];
__device__ float g_msig[TT];

// bf16 activations
__device__ bf16 b_core[TT*DD];
__device__ bf16 b_r[SS*DD];
__device__ bf16 b_rkall[SS*LL*DD];
__device__ bf16 b_x[TT*DD];
__device__ bf16 b_y[TT*DD];
__device__ bf16 b_vec[TT*DD];
__device__ bf16 b_enct[TE*DD];
__device__ bf16 b_h[TT*FF_];
__device__ bf16 b_outb[TT*DD];
__device__ bf16 b_heads[TT*3*DD];
__device__ bf16 b_kvall[(size_t)TE*LL*2*DD];
__device__ bf16 b_q2[TT*DD];
__device__ bf16 b_P[BB*HH*SS*SS];
__device__ bf16 b_P2[BB*HH*SS*EE];

// bf16 weights
__device__ bf16 w_qkv[LL*3*DD*DD];
__device__ bf16 w_r[LL*DD*DD];
__device__ bf16 w_o[LL*DD*DD];
__device__ bf16 w_kv[LL*2*DD*DD];
__device__ bf16 w_q[LL*DD*DD];
__device__ bf16 w_io[LL*DD*DD];
__device__ bf16 w_f1[LL*FF_*DD];
__device__ bf16 w_f2[LL*DD*FF_];
__device__ bf16 w_emb[(size_t)VV*DD];
__device__ bf16 w_out[DD*DD];
__device__ bf16 w_copy[DD*DD];

__device__ __forceinline__ uint32_t smem_u32(const void* p)
{
    return (uint32_t)__cvta_generic_to_shared(p);
}

// ---------------- f32 -> bf16 conversion ----------------
__global__ void cvt_bf16(const float* __restrict__ src, bf16* __restrict__ dst, int n)
{
    int i = (blockIdx.x * 256 + threadIdx.x) * 4;
    if (i >= n) return;
    float4 v = *reinterpret_cast<const float4*>(src + i);
    uint32_t lo = ((uint32_t)__bfloat16_as_ushort(__float2bfloat16_rn(v.y)) << 16)
                | (uint32_t)__bfloat16_as_ushort(__float2bfloat16_rn(v.x));
    uint32_t hi = ((uint32_t)__bfloat16_as_ushort(__float2bfloat16_rn(v.w)) << 16)
                | (uint32_t)__bfloat16_as_ushort(__float2bfloat16_rn(v.z));
    *reinterpret_cast<uint2*>(dst + i) = make_uint2(lo, hi);
}

// ---------------- bf16 tensor-core NT GEMM, 3-stage cp.async, optional split-K ------
// C = A @ Bw^T (+bias, +gelu). BM=BN=128, BK=32. 256 threads = 8 warps (4M x 2N).
// Dynamic smem: 3 stages x (A,B) x 128x40 bf16 = 61440 bytes.
#define SMEMSZ (3*2*128*40*2)
__global__ __launch_bounds__(256, 2)
void sgemm_bf(const bf16* __restrict__ A, const bf16* __restrict__ Bw,
              float* __restrict__ Cf, bf16* __restrict__ Cb,
              const float* __restrict__ bias,
              int K, int lda, int ldb, int ldc, int act, int ksplit)
{
    extern __shared__ bf16 ds[];
    bf16* AsB = ds;                 // [3][128][40]
    bf16* BsB = ds + 3*128*40;

    int tid = threadIdx.x;
    int warp = tid >> 5, lane = tid & 31;
    int warp_m = warp >> 1;
    int warp_n = warp & 1;
    int rowA0 = blockIdx.y * 128;
    int colB0 = blockIdx.x * 128;

    int Kloc = K / ksplit;
    int kgbase = blockIdx.z * Kloc;

    int ldrow = tid >> 1;
    int ldkoff = (tid & 1) * 16;

    float c[2][8][4];
#pragma unroll
    for (int mi = 0; mi < 2; mi++)
#pragma unroll
        for (int ni = 0; ni < 8; ni++)
#pragma unroll
            for (int r = 0; r < 4; r++) c[mi][ni][r] = 0.f;

    const bf16* Agp = &A[(size_t)(rowA0 + ldrow) * lda + kgbase + ldkoff];
    const bf16* Bgp = &Bw[(size_t)(colB0 + ldrow) * ldb + kgbase + ldkoff];

    int nk = Kloc >> 5;
    // prologue: stages 0,1
#pragma unroll
    for (int s = 0; s < 2; s++) {
        bf16* as = AsB + s * (128*40);
        bf16* bs = BsB + s * (128*40);
        uint32_t sa = smem_u32(as + ldrow * 40 + ldkoff);
        uint32_t sb = smem_u32(bs + ldrow * 40 + ldkoff);
        const bf16* ag = Agp + s * 32;
        const bf16* bg = Bgp + s * 32;
        asm volatile("cp.async.ca.shared.global [%0], [%1], 16;\n"
                     "cp.async.ca.shared.global [%2], [%3], 16;\n"
                     "cp.async.ca.shared.global [%4], [%5], 16;\n"
                     "cp.async.ca.shared.global [%6], [%7], 16;\n"
                     :: "r"(sa), "l"(ag), "r"(sa + 16), "l"(ag + 8),
                        "r"(sb), "l"(bg), "r"(sb + 16), "l"(bg + 8));
        asm volatile("cp.async.commit_group;");
    }

    for (int kt = 0; kt < nk; kt++) {
        asm volatile("cp.async.wait_group 1;");
        __syncthreads();
        int pf = kt + 2;
        if (pf < nk) {
            int sbuf = pf - (pf / 3) * 3;
            bf16* as = AsB + sbuf * (128*40);
            bf16* bs = BsB + sbuf * (128*40);
            uint32_t sa = smem_u32(as + ldrow * 40 + ldkoff);
            uint32_t sb = smem_u32(bs + ldrow * 40 + ldkoff);
            const bf16* ag = Agp + pf * 32;
            const bf16* bg = Bgp + pf * 32;
            asm volatile("cp.async.ca.shared.global [%0], [%1], 16;\n"
                         "cp.async.ca.shared.global [%2], [%3], 16;\n"
                         "cp.async.ca.shared.global [%4], [%5], 16;\n"
                         "cp.async.ca.shared.global [%6], [%7], 16;\n"
                         :: "r"(sa), "l"(ag), "r"(sa + 16), "l"(ag + 8),
                            "r"(sb), "l"(bg), "r"(sb + 16), "l"(bg + 8));
        }
        asm volatile("cp.async.commit_group;");

        int cbuf = kt - (kt / 3) * 3;
        bf16* as = AsB + cbuf * (128*40);
        bf16* bs = BsB + cbuf * (128*40);
#pragma unroll
        for (int ks = 0; ks < 2; ks++) {
            int k0 = ks * 16;
            uint32_t a[2][4];
#pragma unroll
            for (int mi = 0; mi < 2; mi++) {
                int m = warp_m * 32 + mi * 16 + (lane & 15);
                int kc = k0 + ((lane >> 4) << 3);
                uint32_t addr = smem_u32(as + m * 40 + kc);
                asm volatile("ldmatrix.sync.aligned.m8n8.x4.shared.b16 {%0,%1,%2,%3}, [%4];"
                             : "=r"(a[mi][0]), "=r"(a[mi][1]), "=r"(a[mi][2]), "=r"(a[mi][3])
                             : "r"(addr));
            }
            uint32_t b[8][2];
#pragma unroll
            for (int nt = 0; nt < 4; nt++) {
                int n = warp_n * 64 + nt * 16 + (lane & 7) + ((lane >> 4) << 3);
                int kc = k0 + (((lane >> 3) & 1) << 3);
                uint32_t addr = smem_u32(bs + n * 40 + kc);
                asm volatile("ldmatrix.sync.aligned.m8n8.x4.shared.b16 {%0,%1,%2,%3}, [%4];"
                             : "=r"(b[nt*2][0]), "=r"(b[nt*2][1]),
                               "=r"(b[nt*2+1][0]), "=r"(b[nt*2+1][1])
                             : "r"(addr));
            }
#pragma unroll
            for (int mi = 0; mi < 2; mi++)
#pragma unroll
                for (int ni = 0; ni < 8; ni++) {
                    asm volatile(
                        "mma.sync.aligned.m16n8k16.row.col.f32.bf16.bf16.f32 "
                        "{%0,%1,%2,%3}, {%4,%5,%6,%7}, {%8,%9}, {%0,%1,%2,%3};\n"
                        : "+f"(c[mi][ni][0]), "+f"(c[mi][ni][1]),
                          "+f"(c[mi][ni][2]), "+f"(c[mi][ni][3])
                        : "r"(a[mi][0]), "r"(a[mi][1]), "r"(a[mi][2]), "r"(a[mi][3]),
                          "r"(b[ni][0]), "r"(b[ni][1]));
                }
        }
    }

    bool addbias = (bias != nullptr) && (blockIdx.z == 0);
#pragma unroll
    for (int mi = 0; mi < 2; mi++) {
        int row0 = rowA0 + warp_m * 32 + mi * 16 + (lane >> 2);
#pragma unroll
        for (int ni = 0; ni < 8; ni++) {
            int col = colB0 + warp_n * 64 + ni * 8 + (lane & 3) * 2;
            float bv0 = 0.f, bv1 = 0.f;
            if (addbias) { bv0 = bias[col]; bv1 = bias[col + 1]; }
#pragma unroll
            for (int half = 0; half < 2; half++) {
                int gm = row0 + half * 8;
                float v0 = c[mi][ni][half * 2 + 0] + bv0;
                float v1 = c[mi][ni][half * 2 + 1] + bv1;
                if (ksplit > 1) {
                    atomicAdd(&Cf[(size_t)gm * ldc + col], v0);
                    atomicAdd(&Cf[(size_t)gm * ldc + col + 1], v1);
                } else {
                    if (act == 1) {
                        v0 = 0.5f * v0 * (1.0f + erff(v0 * 0.70710678118654752f));
                        v1 = 0.5f * v1 * (1.0f + erff(v1 * 0.70710678118654752f));
                    }
                    if (Cf) {
                        Cf[(size_t)gm * ldc + col]     = v0;
                        Cf[(size_t)gm * ldc + col + 1] = v1;
                    }
                    if (Cb) {
                        uint32_t pk = ((uint32_t)__bfloat16_as_ushort(__float2bfloat16_rn(v1)) << 16)
                                    | (uint32_t)__bfloat16_as_ushort(__float2bfloat16_rn(v0));
                        *reinterpret_cast<uint32_t*>(&Cb[(size_t)gm * ldc + col]) = pk;
                    }
                }
            }
        }
    }
}

// ---------------- batched bf16 NT mma (M=128, K=64): scores -------------------------
__global__ __launch_bounds__(256, 2)
void bmm_nt_bf(const bf16* __restrict__ A, const bf16* __restrict__ B,
               float* __restrict__ C, const float* __restrict__ abias,
               int Hdim,
               long long aSB, long long aSH, int aRow,
               long long bSB, long long bSH, int bRow,
               long long cSB, long long cSH, int cRow, int abiasH)
{
    __shared__ bf16 As[128][72];
    __shared__ bf16 Bs[128][72];
    int z = blockIdx.z;
    int h = z % Hdim, b = z / Hdim;
    const bf16* Ab = A + (size_t)b * aSB + (size_t)h * aSH;
    const bf16* Bb = B + (size_t)b * bSB + (size_t)h * bSH + (size_t)blockIdx.x * 128 * bRow;
    float* Cb = C + (size_t)b * cSB + (size_t)h * cSH + blockIdx.x * 128;
    const float* biasb = abias ? (abias + (size_t)h * abiasH) : nullptr;

    int tid = threadIdx.x;
    int warp = tid >> 5, lane = tid & 31;
    int warp_m = warp >> 1, warp_n = warp & 1;
    int row = tid >> 1, koff = (tid & 1) * 32;

    {
        const bf16* ap = Ab + (size_t)row * aRow + koff;
#pragma unroll
        for (int j = 0; j < 4; j++) {
            uint4 v = *reinterpret_cast<const uint4*>(ap + j * 8);
            if (biasb) {
                bf16 tmp[8];
                *reinterpret_cast<uint4*>(tmp) = v;
#pragma unroll
                for (int e = 0; e < 8; e++)
                    tmp[e] = __float2bfloat16_rn(__bfloat162float(tmp[e]) + biasb[koff + j*8 + e]);
                v = *reinterpret_cast<uint4*>(tmp);
            }
            *reinterpret_cast<uint4*>(&As[row][koff + j*8]) = v;
        }
        const bf16* bp = Bb + (size_t)row * bRow + koff;
#pragma unroll
        for (int j = 0; j < 4; j++)
            *reinterpret_cast<uint4*>(&Bs[row][koff + j*8]) = *reinterpret_cast<const uint4*>(bp + j*8);
    }
    __syncthreads();

    float c[2][8][4];
#pragma unroll
    for (int mi = 0; mi < 2; mi++)
#pragma unroll
        for (int ni = 0; ni < 8; ni++)
#pragma unroll
            for (int r = 0; r < 4; r++) c[mi][ni][r] = 0.f;

#pragma unroll
    for (int ks = 0; ks < 4; ks++) {
        int k0 = ks * 16;
        uint32_t a[2][4];
#pragma unroll
        for (int mi = 0; mi < 2; mi++) {
            int m = warp_m * 32 + mi * 16 + (lane & 15);
            int kc = k0 + ((lane >> 4) << 3);
            uint32_t addr = smem_u32(&As[m][kc]);
            asm volatile("ldmatrix.sync.aligned.m8n8.x4.shared.b16 {%0,%1,%2,%3}, [%4];"
                         : "=r"(a[mi][0]), "=r"(a[mi][1]), "=r"(a[mi][2]), "=r"(a[mi][3])
                         : "r"(addr));
        }
        uint32_t bb[8][2];
#pragma unroll
        for (int nt = 0; nt < 4; nt++) {
            int n = warp_n * 64 + nt * 16 + (lane & 7) + ((lane >> 4) << 3);
            int kc = k0 + (((lane >> 3) & 1) << 3);
            uint32_t addr = smem_u32(&Bs[n][kc]);
            asm volatile("ldmatrix.sync.aligned.m8n8.x4.shared.b16 {%0,%1,%2,%3}, [%4];"
                         : "=r"(bb[nt*2][0]), "=r"(bb[nt*2][1]),
                           "=r"(bb[nt*2+1][0]), "=r"(bb[nt*2+1][1])
                         : "r"(addr));
        }
#pragma unroll
        for (int mi = 0; mi < 2; mi++)
#pragma unroll
            for (int ni = 0; ni < 8; ni++) {
                asm volatile(
                    "mma.sync.aligned.m16n8k16.row.col.f32.bf16.bf16.f32 "
                    "{%0,%1,%2,%3}, {%4,%5,%6,%7}, {%8,%9}, {%0,%1,%2,%3};\n"
                    : "+f"(c[mi][ni][0]), "+f"(c[mi][ni][1]),
                      "+f"(c[mi][ni][2]), "+f"(c[mi][ni][3])
                    : "r"(a[mi][0]), "r"(a[mi][1]), "r"(a[mi][2]), "r"(a[mi][3]),
                      "r"(bb[ni][0]), "r"(bb[ni][1]));
            }
    }

#pragma unroll
    for (int mi = 0; mi < 2; mi++) {
        int row0 = warp_m * 32 + mi * 16 + (lane >> 2);
#pragma unroll
        for (int ni = 0; ni < 8; ni++) {
            int col = warp_n * 64 + ni * 8 + (lane & 3) * 2;
#pragma unroll
            for (int half = 0; half < 2; half++) {
                int gm = row0 + half * 8;
                Cb[(size_t)gm * cRow + col]     = c[mi][ni][half*2 + 0];
                Cb[(size_t)gm * cRow + col + 1] = c[mi][ni][half*2 + 1];
            }
        }
    }
}

// ---------------- batched bf16 NN mma (M=128, N=64): C = P @ V ----------------------
__global__ __launch_bounds__(256, 2)
void bmm_nn_bf(const bf16* __restrict__ A, const bf16* __restrict__ B,
               bf16* __restrict__ Cb2,
               int K, int Hdim,
               long long aSB, long long aSH, int aRow,
               long long bSB, long long bSH, int bRow,
               long long cSB, long long cSH, int cRow)
{
    __shared__ bf16 As[128][72];
    __shared__ bf16 Bs[64][72];
    int z = blockIdx.z;
    int h = z % Hdim, b = z / Hdim;
    const bf16* Ab = A + (size_t)b * aSB + (size_t)h * aSH;
    const bf16* Bb = B + (size_t)b * bSB + (size_t)h * bSH;
    bf16* Cb = Cb2 + (size_t)b * cSB + (size_t)h * cSH;

    int tid = threadIdx.x;
    int warp = tid >> 5, lane = tid & 31;
    int warp_m = warp >> 1, warp_n = warp & 1;
    int rowA = tid >> 1, koffA = (tid & 1) * 32;
    int rowB = tid >> 2, doffB = (tid & 3) * 16;

    float c[2][4][4];
#pragma unroll
    for (int mi = 0; mi < 2; mi++)
#pragma unroll
        for (int ni = 0; ni < 4; ni++)
#pragma unroll
            for (int r = 0; r < 4; r++) c[mi][ni][r] = 0.f;

    for (int kb = 0; kb < K; kb += 64) {
        const bf16* ap = Ab + (size_t)rowA * aRow + kb + koffA;
#pragma unroll
        for (int j = 0; j < 4; j++)
            *reinterpret_cast<uint4*>(&As[rowA][koffA + j*8]) =
                *reinterpret_cast<const uint4*>(ap + j*8);
        const bf16* bp = Bb + (size_t)(kb + rowB) * bRow + doffB;
#pragma unroll
        for (int j = 0; j < 2; j++)
            *reinterpret_cast<uint4*>(&Bs[rowB][doffB + j*8]) =
                *reinterpret_cast<const uint4*>(bp + j*8);
        __syncthreads();

#pragma unroll
        for (int ks = 0; ks < 4; ks++) {
            int k0 = ks * 16;
            uint32_t a[2][4];
#pragma unroll
            for (int mi = 0; mi < 2; mi++) {
                int m = warp_m * 32 + mi * 16 + (lane & 15);
                int kc = k0 + ((lane >> 4) << 3);
                uint32_t addr = smem_u32(&As[m][kc]);
                asm volatile("ldmatrix.sync.aligned.m8n8.x4.shared.b16 {%0,%1,%2,%3}, [%4];"
                             : "=r"(a[mi][0]), "=r"(a[mi][1]), "=r"(a[mi][2]), "=r"(a[mi][3])
                             : "r"(addr));
            }
            uint32_t bb[4][2];
#pragma unroll
            for (int nt = 0; nt < 2; nt++) {
                int kr = k0 + (lane & 15);
                int n = warp_n * 32 + nt * 16 + ((lane >> 4) << 3);
                uint32_t addr = smem_u32(&Bs[kr][n]);
                asm volatile("ldmatrix.sync.aligned.m8n8.x4.trans.shared.b16 {%0,%1,%2,%3}, [%4];"
                             : "=r"(bb[nt*2][0]), "=r"(bb[nt*2][1]),
                               "=r"(bb[nt*2+1][0]), "=r"(bb[nt*2+1][1])
                             : "r"(addr));
            }
#pragma unroll
            for (int mi = 0; mi < 2; mi++)
#pragma unroll
                for (int ni = 0; ni < 4; ni++) {
                    asm volatile(
                        "mma.sync.aligned.m16n8k16.row.col.f32.bf16.bf16.f32 "
                        "{%0,%1,%2,%3}, {%4,%5,%6,%7}, {%8,%9}, {%0,%1,%2,%3};\n"
                        : "+f"(c[mi][ni][0]), "+f"(c[mi][ni][1]),
                          "+f"(c[mi][ni][2]), "+f"(c[mi][ni][3])
                        : "r"(a[mi][0]), "r"(a[mi][1]), "r"(a[mi][2]), "r"(a[mi][3]),
                          "r"(bb[ni][0]), "r"(bb[ni][1]));
                }
        }
        __syncthreads();
    }

#pragma unroll
    for (int mi = 0; mi < 2; mi++) {
        int row0 = warp_m * 32 + mi * 16 + (lane >> 2);
#pragma unroll
        for (int ni = 0; ni < 4; ni++) {
            int col = warp_n * 32 + ni * 8 + (lane & 3) * 2;
#pragma unroll
            for (int half = 0; half < 2; half++) {
                int gm = row0 + half * 8;
                uint32_t pk = ((uint32_t)__bfloat16_as_ushort(__float2bfloat16_rn(c[mi][ni][half*2+1])) << 16)
                            | (uint32_t)__bfloat16_as_ushort(__float2bfloat16_rn(c[mi][ni][half*2+0]));
                *reinterpret_cast<uint32_t*>(&Cb[(size_t)gm * cRow + col]) = pk;
            }
        }
    }
}

// ---------------- batched fp32 NT gemm (copy-attn IL only) ---------------------------
__global__ __launch_bounds__(256, 2)
void bgemm_nt(const float* __restrict__ A, const float* __restrict__ Bp,
              float* __restrict__ C,
              int K,
              long long aSB, int aRow,
              long long bSB, int bRow,
              long long cSB, int cRow)
{
    __shared__ float As[16][132];
    __shared__ float Bs[16][132];
    int b = blockIdx.z;
    const float* Ab = A + (size_t)b * aSB;
    const float* Bb = Bp + (size_t)b * bSB;
    float* Cb = C + (size_t)b * cSB;

    int tid = threadIdx.x;
    int tx = tid & 15, ty = tid >> 4;
    int m0 = ty * 8, n0 = tx * 8;
    int colB0 = blockIdx.x * 128;
    int r  = tid >> 2;
    int c4 = (tid & 3) * 4;
    float acc[8][8];
#pragma unroll
    for (int i = 0; i < 8; i++)
#pragma unroll
        for (int j = 0; j < 8; j++) acc[i][j] = 0.f;

    for (int kb = 0; kb < K; kb += 16) {
#pragma unroll
        for (int half = 0; half < 2; half++) {
            int rr = r + half * 64;
            float4 av = *reinterpret_cast<const float4*>(&Ab[(size_t)rr * aRow + kb + c4]);
            As[c4+0][rr] = av.x; As[c4+1][rr] = av.y; As[c4+2][rr] = av.z; As[c4+3][rr] = av.w;
            float4 bv = *reinterpret_cast<const float4*>(&Bb[(size_t)(colB0 + rr) * bRow + kb + c4]);
            Bs[c4+0][rr] = bv.x; Bs[c4+1][rr] = bv.y; Bs[c4+2][rr] = bv.z; Bs[c4+3][rr] = bv.w;
        }
        __syncthreads();
#pragma unroll
        for (int kk = 0; kk < 16; kk++) {
            float a[8], bb[8];
            *reinterpret_cast<float4*>(a)      = *reinterpret_cast<const float4*>(&As[kk][m0]);
            *reinterpret_cast<float4*>(a + 4)  = *reinterpret_cast<const float4*>(&As[kk][m0 + 4]);
            *reinterpret_cast<float4*>(bb)     = *reinterpret_cast<const float4*>(&Bs[kk][n0]);
            *reinterpret_cast<float4*>(bb + 4) = *reinterpret_cast<const float4*>(&Bs[kk][n0 + 4]);
#pragma unroll
            for (int i = 0; i < 8; i++)
#pragma unroll
                for (int j = 0; j < 8; j++) acc[i][j] += a[i] * bb[j];
        }
        __syncthreads();
    }
#pragma unroll
    for (int i = 0; i < 8; i++)
#pragma unroll
        for (int j = 0; j < 8; j++)
            Cb[(size_t)(m0 + i) * cRow + colB0 + n0 + j] = acc[i][j];
}

// ---------------- misc small kernels --------------------------------------------------
__global__ void pos_emb_kernel(float* __restrict__ r, bf16* __restrict__ rb)
{
    int i = blockIdx.x;
    float pos = (float)(SS - 1 - i);
    const float LOG1E4 = 9.210340371976184f;
    for (int d = threadIdx.x; d < DD; d += 256) {
        int j = (d < DD/2) ? d : d - DD/2;
        float invf = expf(-((float)j / (DD/2)) * LOG1E4);
        float a = pos * invf;
        float v = (d < DD/2) ? sinf(a) : cosf(a);
        r[i * DD + d] = v;
        rb[i * DD + d] = __float2bfloat16_rn(v);
    }
}

__global__ void embed_kernel(const int* __restrict__ dec, const float* __restrict__ emb,
                             float* __restrict__ core, bf16* __restrict__ coreb)
{
    int t = blockIdx.x;
    int b = t & (BB-1), s = t >> 3;
    int id = dec[b * SS + s];
    const float* src = emb + (size_t)id * DD;
    for (int d = threadIdx.x; d < DD; d += 256) {
        float v = src[d];
        core[(size_t)t * DD + d] = v;
        coreb[(size_t)t * DD + d] = __float2bfloat16_rn(v);
    }
}

__global__ void transpose_enc(const float* __restrict__ enc, float* __restrict__ enct,
                              bf16* __restrict__ enctb)
{
    int t = blockIdx.x;
    int b = t & (BB-1), e = t >> 3;
    const float* src = enc + ((size_t)b * EE + e) * DD;
    for (int d = threadIdx.x; d < DD; d += 256) {
        float v = src[d];
        enct[(size_t)t * DD + d] = v;
        enctb[(size_t)t * DD + d] = __float2bfloat16_rn(v);
    }
}

__global__ void softmax_self(const float* __restrict__ AC, const float* __restrict__ BD,
                             bf16* __restrict__ P)
{
    int row = blockIdx.x;
    int i = row & (SS - 1);
    int bhBase = row - i;
    int j = threadIdx.x;
    float acv = AC[(size_t)row * SS + j];
    int f = i * SS + j + SS;
    int qi = f / (SS + 1), c = f % (SS + 1);
    float bd = (c > 0) ? BD[(size_t)(bhBase + qi) * SS + (c - 1)] : 0.0f;
    float s = (acv + bd) * SCALE_;
    if (j > i) s = NEG_;
    __shared__ float sh[128];
    sh[j] = s; __syncthreads();
    for (int st = 64; st > 0; st >>= 1) { if (j < st) sh[j] = fmaxf(sh[j], sh[j + st]); __syncthreads(); }
    float mx = sh[0]; __syncthreads();
    float e = expf(s - mx);
    sh[j] = e; __syncthreads();
    for (int st = 64; st > 0; st >>= 1) { if (j < st) sh[j] += sh[j + st]; __syncthreads(); }
    P[(size_t)row * SS + j] = __float2bfloat16_rn(e / sh[0]);
}

__global__ void softmax_cross(const float* __restrict__ S2, const float* __restrict__ mask,
                              bf16* __restrict__ P)
{
    int row = blockIdx.x;
    int b = row / (HH * SS);
    int k = threadIdx.x;
    float v = S2[(size_t)row * EE + k] * SCALE_ + (1.0f - mask[b * EE + k]) * NEG_;
    __shared__ float sh[512];
    sh[k] = v; __syncthreads();
    for (int st = 256; st > 0; st >>= 1) { if (k < st) sh[k] = fmaxf(sh[k], sh[k + st]); __syncthreads(); }
    float mx = sh[0]; __syncthreads();
    float e = expf(v - mx);
    sh[k] = e; __syncthreads();
    for (int st = 256; st > 0; st >>= 1) { if (k < st) sh[k] += sh[k + st]; __syncthreads(); }
    P[(size_t)row * EE + k] = __float2bfloat16_rn(e / sh[0]);
}

__global__ void softmax_il(float* __restrict__ IL, const float* __restrict__ mask)
{
    int t = blockIdx.x;
    int b = t & (BB - 1);
    int k = threadIdx.x;
    float v = IL[(size_t)t * EE + k] + (1.0f - mask[b * EE + k]) * NEG_;
    __shared__ float sh[512];
    sh[k] = v; __syncthreads();
    for (int st = 256; st > 0; st >>= 1) { if (k < st) sh[k] = fmaxf(sh[k], sh[k + st]); __syncthreads(); }
    float mx = sh[0]; __syncthreads();
    float e = expf(v - mx);
    sh[k] = e; __syncthreads();
    for (int st = 256; st > 0; st >>= 1) { if (k < st) sh[k] += sh[k + st]; __syncthreads(); }
    IL[(size_t)t * EE + k] = e / sh[0];
}

__global__ void add_ln(const float* __restrict__ resid, const float* __restrict__ add,
                       float* __restrict__ out, bf16* __restrict__ outb,
                       const float* __restrict__ g, const float* __restrict__ bta)
{
    int t = blockIdx.x;
    int tid = threadIdx.x;
    __shared__ float zb[DD];
    __shared__ float red[256];
    float s = 0.f;
#pragma unroll
    for (int u = 0; u < 4; u++) {
        int d = tid + u * 256;
        float z = resid[(size_t)t * DD + d] + add[(size_t)t * DD + d];
        zb[d] = z; s += z;
    }
    red[tid] = s; __syncthreads();
    for (int st = 128; st > 0; st >>= 1) { if (tid < st) red[tid] += red[tid + st]; __syncthreads(); }
    float mean = red[0] * (1.0f / DD); __syncthreads();
    float v = 0.f;
#pragma unroll
    for (int u = 0; u < 4; u++) {
        int d = tid + u * 256;
        float dz = zb[d] - mean; v += dz * dz;
    }
    red[tid] = v; __syncthreads();
    for (int st = 128; st > 0; st >>= 1) { if (tid < st) red[tid] += red[tid + st]; __syncthreads(); }
    float inv = rsqrtf(red[0] * (1.0f / DD) + 1e-5f);
#pragma unroll
    for (int u = 0; u < 4; u++) {
        int d = tid + u * 256;
        float o = (zb[d] - mean) * inv * g[d] + bta[d];
        out[(size_t)t * DD + d] = o;
        if (outb) outb[(size_t)t * DD + d] = __float2bfloat16_rn(o);
    }
}

__global__ void row_logit_stats(const float* __restrict__ Lg, float* __restrict__ rmax,
                                float* __restrict__ rsum)
{
    int t = blockIdx.x;
    int tid = threadIdx.x;
    const float* row = Lg + (size_t)t * VV;
    float m = -1e30f;
    for (int v = tid * 4; v < VV; v += 1024) {
        float4 x = *reinterpret_cast<const float4*>(row + v);
        m = fmaxf(m, fmaxf(fmaxf(x.x, x.y), fmaxf(x.z, x.w)));
    }
    __shared__ float red[256];
    red[tid] = m; __syncthreads();
    for (int st = 128; st > 0; st >>= 1) { if (tid < st) red[tid] = fmaxf(red[tid], red[tid + st]); __syncthreads(); }
    m = red[0]; __syncthreads();
    float s = 0.f;
    for (int v = tid * 4; v < VV; v += 1024) {
        float4 x = *reinterpret_cast<const float4*>(row + v);
        s += expf(x.x - m) + expf(x.y - m) + expf(x.z - m) + expf(x.w - m);
    }
    red[tid] = s; __syncthreads();
    for (int st = 128; st > 0; st >>= 1) { if (tid < st) red[tid] += red[tid + st]; __syncthreads(); }
    if (tid == 0) { rmax[t] = m; rsum[t] = red[0]; }
}

__global__ void mode_kernel(const float* __restrict__ core, const float* __restrict__ mw,
                            const float* __restrict__ mb, float* __restrict__ msig)
{
    int t = blockIdx.x;
    int tid = threadIdx.x;
    float s = 0.f;
    for (int d = tid; d < DD; d += 256) s += core[(size_t)t * DD + d] * mw[d];
    __shared__ float red[256];
    red[tid] = s; __syncthreads();
    for (int st = 128; st > 0; st >>= 1) { if (tid < st) red[tid] += red[tid + st]; __syncthreads(); }
    if (tid == 0) msig[t] = 1.0f / (1.0f + expf(-(red[0] + mb[0])));
}

__global__ void loss_kernel(const float* __restrict__ logits, const float* __restrict__ rmax,
                            const float* __restrict__ rsum, const float* __restrict__ msig,
                            const float* __restrict__ IL, const int* __restrict__ input_ids,
                            const int* __restrict__ decode_target, float* __restrict__ out)
{
    int tid = threadIdx.x;
    float acc = 0.f, cnt = 0.f;
    for (int t = tid; t < TT; t += 256) {
        int b = t & (BB - 1), s = t >> 3;
        int tgt = decode_target[b * SS + s];
        if (tgt == 0) continue;
        float m = msig[t];
        float p = expf(logits[(size_t)t * VV + tgt] - rmax[t]) / rsum[t] * m;
        const int* ids = input_ids + b * EE;
        const float* il = IL + (size_t)t * EE;
        float cp = 0.f;
        for (int j = 0; j < EE; j++) if (ids[j] == tgt) cp += il[j];
        p += (1.0f - m) * cp;
        acc += -logf(p + 1e-6f);
        cnt += 1.0f;
    }
    __shared__ float sa[256], sc[256];
    sa[tid] = acc; sc[tid] = cnt; __syncthreads();
    for (int st = 128; st > 0; st >>= 1) {
        if (tid < st) { sa[tid] += sa[tid + st]; sc[tid] += sc[tid + st]; }
        __syncthreads();
    }
    if (tid < BB) out[tid] = sa[0] / sc[0];
}

// ---------------- host orchestration --------------------------------------------------
static void* symaddr(const void* sym)
{
    void* p = nullptr;
    cudaGetSymbolAddress(&p, sym);
    return p;
}

static void cvt(const float* src, bf16* dst, size_t n)
{
    int blocks = (int)((n / 4 + 255) / 256);
    cvt_bf16<<<blocks, 256>>>(src, dst, (int)n);
}

extern "C" void kernel_launch(void* const* d_in, const int* in_sizes, int n_in,
                              void* d_out, int out_size)
{
    const int*   input_ids     = (const int*)d_in[0];
    const float* encoder_rep   = (const float*)d_in[1];
    const float* input_mask    = (const float*)d_in[2];
    const int*   decode_input  = (const int*)d_in[3];
    const int*   decode_target = (const int*)d_in[4];
    const float* word_emb      = (const float*)d_in[5];
    const float* qkv_w         = (const float*)d_in[6];
    const float* r_w           = (const float*)d_in[7];
    const float* o_w           = (const float*)d_in[8];
    const float* kv_w          = (const float*)d_in[9];
    const float* q_w           = (const float*)d_in[10];
    const float* io_w          = (const float*)d_in[11];
    const float* rr_bias       = (const float*)d_in[12];
    const float* rw_bias       = (const float*)d_in[13];
    const float* ln1_g         = (const float*)d_in[14];
    const float* ln1_b         = (const float*)d_in[15];
    const float* ln2_g         = (const float*)d_in[16];
    const float* ln2_b         = (const float*)d_in[17];
    const float* ffn_w1        = (const float*)d_in[18];
    const float* ffn_b1        = (const float*)d_in[19];
    const float* ffn_w2        = (const float*)d_in[20];
    const float* ffn_b2        = (const float*)d_in[21];
    const float* ln3_g         = (const float*)d_in[22];
    const float* ln3_b         = (const float*)d_in[23];
    const float* out_w         = (const float*)d_in[24];
    const float* out_b         = (const float*)d_in[25];
    const float* copy_w        = (const float*)d_in[26];
    const float* copy_b        = (const float*)d_in[27];
    const float* mode_w        = (const float*)d_in[28];
    const float* mode_b        = (const float*)d_in[29];

    float* p_r     = (float*)symaddr(g_r);
    float* p_core  = (float*)symaddr(g_core);
    float* p_x     = (float*)symaddr(g_x);
    float* p_y     = (float*)symaddr(g_y);
    float* p_tmp   = (float*)symaddr(g_tmp);
    float* p_copyh = (float*)symaddr(g_copyh);
    float* p_enct  = (float*)symaddr(g_enct);
    float* p_AC    = (float*)symaddr(g_AC);
    float* p_BD    = (float*)symaddr(g_BD);
    float* p_s2    = (float*)symaddr(g_s2);
    float* p_log   = (float*)symaddr(g_logits);
    float* p_IL    = (float*)symaddr(g_IL);
    float* p_rmax  = (float*)symaddr(g_rmax);
    float* p_rsum  = (float*)symaddr(g_rsum);
    float* p_msig  = (float*)symaddr(g_msig);

    bf16* pb_core = (bf16*)symaddr(b_core);
    bf16* pb_r    = (bf16*)symaddr(b_r);
    bf16* pb_rkall= (bf16*)symaddr(b_rkall);
    bf16* pb_x    = (bf16*)symaddr(b_x);
    bf16* pb_y    = (bf16*)symaddr(b_y);
    bf16* pb_vec  = (bf16*)symaddr(b_vec);
    bf16* pb_enct = (bf16*)symaddr(b_enct);
    bf16* pb_h    = (bf16*)symaddr(b_h);
    bf16* pb_outb = (bf16*)symaddr(b_outb);
    bf16* pb_heads= (bf16*)symaddr(b_heads);
    bf16* pb_kvall= (bf16*)symaddr(b_kvall);
    bf16* pb_q2   = (bf16*)symaddr(b_q2);
    bf16* pb_P    = (bf16*)symaddr(b_P);
    bf16* pb_P2   = (bf16*)symaddr(b_P2);

    bf16* pw_qkv = (bf16*)symaddr(w_qkv);
    bf16* pw_r   = (bf16*)symaddr(w_r);
    bf16* pw_o   = (bf16*)symaddr(w_o);
    bf16* pw_kv  = (bf16*)symaddr(w_kv);
    bf16* pw_q   = (bf16*)symaddr(w_q);
    bf16* pw_io  = (bf16*)symaddr(w_io);
    bf16* pw_f1  = (bf16*)symaddr(w_f1);
    bf16* pw_f2  = (bf16*)symaddr(w_f2);
    bf16* pw_emb = (bf16*)symaddr(w_emb);
    bf16* pw_out = (bf16*)symaddr(w_out);
    bf16* pw_cp  = (bf16*)symaddr(w_copy);

    cudaFuncSetAttribute(sgemm_bf, cudaFuncAttributeMaxDynamicSharedMemorySize, SMEMSZ);

    cvt(qkv_w,  pw_qkv, (size_t)LL*3*DD*DD);
    cvt(r_w,    pw_r,   (size_t)LL*DD*DD);
    cvt(o_w,    pw_o,   (size_t)LL*DD*DD);
    cvt(kv_w,   pw_kv,  (size_t)LL*2*DD*DD);
    cvt(q_w,    pw_q,   (size_t)LL*DD*DD);
    cvt(io_w,   pw_io,  (size_t)LL*DD*DD);
    cvt(ffn_w1, pw_f1,  (size_t)LL*FF_*DD);
    cvt(ffn_w2, pw_f2,  (size_t)LL*DD*FF_);
    cvt(word_emb, pw_emb, (size_t)VV*DD);
    cvt(out_w,  pw_out, (size_t)DD*DD);
    cvt(copy_w, pw_cp,  (size_t)DD*DD);

    pos_emb_kernel<<<SS, 256>>>(p_r, pb_r);
    embed_kernel<<<TT, 256>>>(decode_input, word_emb, p_core, pb_core);
    transpose_enc<<<TE, 256>>>(encoder_rep, p_enct, pb_enct);

    // layer-invariant GEMMs hoisted: rk (all layers), kv (all layers)
    sgemm_bf<<<dim3(LL*DD/128, SS/128), 256, SMEMSZ>>>(pb_r, pw_r, nullptr, pb_rkall,
                                                       nullptr, DD, DD, DD, LL*DD, 0, 1);
    sgemm_bf<<<dim3(LL*2*DD/128, TE/128), 256, SMEMSZ>>>(pb_enct, pw_kv, nullptr, pb_kvall,
                                                         nullptr, DD, DD, DD, LL*2*DD, 0, 1);

    for (int l = 0; l < LL; l++) {
        sgemm_bf<<<dim3(3*DD/128, TT/128), 256, SMEMSZ>>>(pb_core, pw_qkv + (size_t)l*3*DD*DD,
            nullptr, pb_heads, nullptr, DD, DD, DD, 3*DD, 0, 1);
        // AC = (q + rw_bias) . k
        bmm_nt_bf<<<dim3(1, 1, BB*HH), 256>>>(pb_heads, pb_heads + DD, p_AC,
            rw_bias + (size_t)l*HH*DHH, HH,
            3*DD, DHH, BB*3*DD,
            3*DD, DHH, BB*3*DD,
            (long long)HH*SS*SS, (long long)SS*SS, SS, DHH);
        // BD = (q + rr_bias) . r_k   (rk from hoisted buffer: row stride LL*DD)
        bmm_nt_bf<<<dim3(1, 1, BB*HH), 256>>>(pb_heads, pb_rkall + (size_t)l*DD, p_BD,
            rr_bias + (size_t)l*HH*DHH, HH,
            3*DD, DHH, BB*3*DD,
            0, DHH, LL*DD,
            (long long)HH*SS*SS, (long long)SS*SS, SS, DHH);
        softmax_self<<<BB*HH*SS, 128>>>(p_AC, p_BD, pb_P);
        bmm_nn_bf<<<dim3(1, 1, BB*HH), 256>>>(pb_P, pb_heads + 2*DD, pb_vec,
            SS, HH,
            (long long)HH*SS*SS, (long long)SS*SS, SS,
            3*DD, DHH, BB*3*DD,
            DD, DHH, BB*DD);
        // o projection: split-K 2 with atomic f32 accumulate
        cudaMemsetAsync(p_tmp, 0, (size_t)TT*DD*sizeof(float), 0);
        sgemm_bf<<<dim3(DD/128, TT/128, 2), 256, SMEMSZ>>>(pb_vec, pw_o + (size_t)l*DD*DD,
            p_tmp, nullptr, nullptr, DD, DD, DD, DD, 0, 2);
        add_ln<<<TT, 256>>>(p_core, p_tmp, p_x, pb_x, ln1_g + l*DD, ln1_b + l*DD);

        // cross attention (kv from hoisted buffer)
        sgemm_bf<<<dim3(DD/128, TT/128), 256, SMEMSZ>>>(pb_x, pw_q + (size_t)l*DD*DD,
            nullptr, pb_q2, nullptr, DD, DD, DD, DD, 0, 1);
        bmm_nt_bf<<<dim3(EE/128, 1, BB*HH), 256>>>(pb_q2, pb_kvall + (size_t)l*2*DD, p_s2,
            nullptr, HH,
            DD, DHH, BB*DD,
            (long long)LL*2*DD, DHH, BB*LL*2*DD,
            (long long)HH*SS*EE, (long long)SS*EE, EE, 0);
        softmax_cross<<<BB*HH*SS, 512>>>(p_s2, input_mask, pb_P2);
        bmm_nn_bf<<<dim3(1, 1, BB*HH), 256>>>(pb_P2, pb_kvall + (size_t)l*2*DD + DD, pb_vec,
            EE, HH,
            (long long)HH*SS*EE, (long long)SS*EE, EE,
            (long long)LL*2*DD, DHH, BB*LL*2*DD,
            DD, DHH, BB*DD);
        cudaMemsetAsync(p_tmp, 0, (size_t)TT*DD*sizeof(float), 0);
        sgemm_bf<<<dim3(DD/128, TT/128, 2), 256, SMEMSZ>>>(pb_vec, pw_io + (size_t)l*DD*DD,
            p_tmp, nullptr, nullptr, DD, DD, DD, DD, 0, 2);
        add_ln<<<TT, 256>>>(p_x, p_tmp, p_y, pb_y, ln2_g + l*DD, ln2_b + l*DD);

        // FFN
        sgemm_bf<<<dim3(FF_/128, TT/128), 256, SMEMSZ>>>(pb_y, pw_f1 + (size_t)l*FF_*DD,
            nullptr, pb_h, ffn_b1 + (size_t)l*FF_, DD, DD, DD, FF_, 1, 1);
        cudaMemsetAsync(p_tmp, 0, (size_t)TT*DD*sizeof(float), 0);
        sgemm_bf<<<dim3(DD/128, TT/128, 4), 256, SMEMSZ>>>(pb_h, pw_f2 + (size_t)l*DD*FF_,
            p_tmp, nullptr, ffn_b2 + (size_t)l*DD, FF_, FF_, FF_, DD, 0, 4);
        add_ln<<<TT, 256>>>(p_y, p_tmp, p_core, pb_core, ln3_g + l*DD, ln3_b + l*DD);
    }

    // output head
    sgemm_bf<<<dim3(DD/128, TT/128), 256, SMEMSZ>>>(pb_core, pw_out, nullptr, pb_outb, out_b,
                                                    DD, DD, DD, DD, 0, 1);
    sgemm_bf<<<dim3(VV/128, TT/128), 256, SMEMSZ>>>(pb_outb, pw_emb, p_log, nullptr, nullptr,
                                                    DD, DD, DD, VV, 0, 1);
    row_logit_stats<<<TT, 256>>>(p_log, p_rmax, p_rsum);

    sgemm_bf<<<dim3(DD/128, TT/128), 256, SMEMSZ>>>(pb_core, pw_cp, p_copyh, nullptr, copy_b,
                                                    DD, DD, DD, DD, 0, 1);
    bgemm_nt<<<dim3(EE/128, 1, BB), 256>>>(p_copyh, p_enct, p_IL,
        DD,
        DD, BB*DD,
        DD, BB*DD,
        EE, BB*EE);
    softmax_il<<<TT, 512>>>(p_IL, input_mask);
    mode_kernel<<<TT, 256>>>(p_core, mode_w, mode_b, p_msig);
    loss_kernel<<<1, 256>>>(p_log, p_rmax, p_rsum, p_msig, p_IL, input_ids, decode_target,
                            (float*)d_out);
}